// round 5
// baseline (speedup 1.0000x reference)
#include <cuda_runtime.h>
#include <cuda_bf16.h>
#include <stdint.h>
#include <math.h>

#define BATCH  65536
#define D_DIM  256
#define W_DIM  1024
#define MTILE  64
#define CW     32
#define NCHUNK (W_DIM / CW)    // 32

// bf16 hi/lo split images (natural row-major) in device scratch
__device__ __align__(16) __nv_bfloat16 g_z_hi[(size_t)BATCH * D_DIM];
__device__ __align__(16) __nv_bfloat16 g_z_lo[(size_t)BATCH * D_DIM];
__device__ __align__(16) __nv_bfloat16 g_w1_hi[W_DIM * D_DIM];
__device__ __align__(16) __nv_bfloat16 g_w1_lo[W_DIM * D_DIM];
__device__ __align__(16) __nv_bfloat16 g_w2_hi[D_DIM * W_DIM];
__device__ __align__(16) __nv_bfloat16 g_w2_lo[D_DIM * W_DIM];
__device__ float g_M[W_DIM];

// ---------------- SMEM layout (bytes) ----------------
// z  : [64][264] bf16 hi + lo, stride 528B
// W1 : double-buffered chunk [32][264] bf16 hi+lo per buffer
// W2 : double-buffered chunk [256][40] bf16 hi+lo per buffer, stride 80B
// h  : [64][40] bf16 hi+lo, stride 80B
#define ZS      528
#define W2S     80
#define HS      80

#define S_Z     0            // z hi; z lo at +33792
#define DLO_Z   33792
#define S_W1    67584        // buffer b at +b*33792; lo at +16896
#define W1BUF   33792
#define DLO_W1  16896
#define S_W2    135168       // buffer b at +b*40960; lo at +20480
#define W2BUF   40960
#define DLO_W2  20480
#define S_H     217088       // hi; lo at +5120
#define DLO_H   5120
#define TR_OFF  227328
#define S_TOTAL 227584

// ---------------- PTX helpers ----------------
__device__ __forceinline__ uint32_t smem_u32(const void* p) {
    uint32_t a;
    asm("{ .reg .u64 t; cvta.to.shared.u64 t, %1; cvt.u32.u64 %0, t; }" : "=r"(a) : "l"(p));
    return a;
}
#define CP_ASYNC16(d, s) \
    asm volatile("cp.async.cg.shared.global [%0], [%1], 16;" :: "r"(d), "l"(s))
#define CP_COMMIT() asm volatile("cp.async.commit_group;")
#define CP_WAIT0()  asm volatile("cp.async.wait_group 0;")

#define LDSM4(r, addr) \
    asm volatile("ldmatrix.sync.aligned.m8n8.x4.shared.b16 {%0,%1,%2,%3}, [%4];" \
        : "=r"((r)[0]), "=r"((r)[1]), "=r"((r)[2]), "=r"((r)[3]) : "r"(addr))
#define LDSM2(r, addr) \
    asm volatile("ldmatrix.sync.aligned.m8n8.x2.shared.b16 {%0,%1}, [%2];" \
        : "=r"((r)[0]), "=r"((r)[1]) : "r"(addr))

__device__ __forceinline__ void mma_bf16(float* c, const uint32_t* a, uint32_t b0, uint32_t b1) {
    asm volatile(
        "mma.sync.aligned.m16n8k16.row.col.f32.bf16.bf16.f32 "
        "{%0,%1,%2,%3}, {%4,%5,%6,%7}, {%8,%9}, {%0,%1,%2,%3};"
        : "+f"(c[0]), "+f"(c[1]), "+f"(c[2]), "+f"(c[3])
        : "r"(a[0]), "r"(a[1]), "r"(a[2]), "r"(a[3]), "r"(b0), "r"(b1));
}

// ---------------- split pre-pass ----------------
union Pack8 { uint4 u; __nv_bfloat16 b[8]; };

__global__ void split_kernel(const float* __restrict__ src,
                             __nv_bfloat16* __restrict__ dhi,
                             __nv_bfloat16* __restrict__ dlo) {
    size_t gid = (size_t)blockIdx.x * 256 + threadIdx.x;
    const float4* s = reinterpret_cast<const float4*>(src);
    float4 a = s[gid * 2], b = s[gid * 2 + 1];
    float v[8] = {a.x, a.y, a.z, a.w, b.x, b.y, b.z, b.w};
    Pack8 hi, lo;
    #pragma unroll
    for (int i = 0; i < 8; i++) {
        __nv_bfloat16 h = __float2bfloat16_rn(v[i]);
        hi.b[i] = h;
        lo.b[i] = __float2bfloat16_rn(v[i] - __bfloat162float(h));
    }
    reinterpret_cast<uint4*>(dhi)[gid] = hi.u;
    reinterpret_cast<uint4*>(dlo)[gid] = lo.u;
}

__global__ void compute_M_kernel(const float* __restrict__ W1, const float* __restrict__ W2) {
    int j = blockIdx.x, i = threadIdx.x;
    float v = W1[j * D_DIM + i] * W2[(size_t)i * W_DIM + j];
    #pragma unroll
    for (int o = 16; o > 0; o >>= 1) v += __shfl_down_sync(0xffffffffu, v, o);
    __shared__ float red[8];
    if ((i & 31) == 0) red[i >> 5] = v;
    __syncthreads();
    if (i < 8) {
        float s = red[i];
        #pragma unroll
        for (int o = 4; o > 0; o >>= 1) s += __shfl_down_sync(0xffu, s, o);
        if (i == 0) g_M[j] = s;
    }
}

// ---------------- copy helpers (cp.async) ----------------
// z: 64 rows x 256 bf16 (hi and lo) -> stride 528
__device__ __forceinline__ void cp_z(uint32_t sb, const __nv_bfloat16* ghi,
                                     const __nv_bfloat16* glo) {
    for (int i = threadIdx.x; i < 4096; i += 256) {
        int part = i >> 11, idx = i & 2047;
        int r = idx >> 5, c = idx & 31;
        const __nv_bfloat16* g = part ? glo : ghi;
        CP_ASYNC16(sb + S_Z + part * DLO_Z + r * ZS + c * 16, g + r * 256 + c * 8);
    }
}
// W1 chunk: 32 rows x 256 bf16 hi+lo -> buffer b, stride 528
__device__ __forceinline__ void cp_w1(uint32_t sb, int b, int jc) {
    uint32_t base = sb + S_W1 + b * W1BUF;
    for (int i = threadIdx.x; i < 2048; i += 256) {
        int part = i >> 10, idx = i & 1023;
        int r = idx >> 5, c = idx & 31;
        const __nv_bfloat16* g = (part ? g_w1_lo : g_w1_hi) + (size_t)(jc + r) * 256 + c * 8;
        CP_ASYNC16(base + part * DLO_W1 + r * ZS + c * 16, g);
    }
}
// W2 chunk: 256 rows x 32 bf16 hi+lo -> buffer b, stride 80
__device__ __forceinline__ void cp_w2(uint32_t sb, int b, int jc) {
    uint32_t base = sb + S_W2 + b * W2BUF;
    for (int i = threadIdx.x; i < 2048; i += 256) {
        int part = i >> 10, idx = i & 1023;
        int r = idx >> 2, c = idx & 3;
        const __nv_bfloat16* g = (part ? g_w2_lo : g_w2_hi) + (size_t)r * W_DIM + jc + c * 8;
        CP_ASYNC16(base + part * DLO_W2 + r * W2S + c * 16, g);
    }
}

// ---------------- main fused kernel ----------------
__global__ void __launch_bounds__(256, 1)
planar_mma_kernel(const float* __restrict__ b1,
                  float* __restrict__ dz_out,
                  float* __restrict__ dlog_out) {
    extern __shared__ char smem[];
    const uint32_t sb = smem_u32(smem);
    float* sTr = reinterpret_cast<float*>(smem + TR_OFF);

    const int tid  = threadIdx.x;
    const int wid  = tid >> 5;
    const int lane = tid & 31;
    const int mg   = wid >> 2;     // 0/1 : rows 32*mg..+31
    const int ng   = wid & 3;      // GEMM1: 8 cols; GEMM2: 64 cols
    const int row0 = blockIdx.x * MTILE;

    if (tid < MTILE) sTr[tid] = 0.0f;

    // prologue: z + chunk-0 weights
    cp_z(sb, g_z_hi + (size_t)row0 * D_DIM, g_z_lo + (size_t)row0 * D_DIM);
    cp_w1(sb, 0, 0);
    cp_w2(sb, 0, 0);
    CP_COMMIT();
    CP_WAIT0();
    __syncthreads();

    // per-lane ldmatrix addressing
    const int lrow16 = lane & 15;
    const int lkhalf = (lane >> 4) << 3;
    const int brow   = (lane & 7) + ((lane >> 4) << 3);    // 16-row B frags (W2)
    const int bkhalf = ((lane >> 3) & 1) << 3;

    const uint32_t aZ0 = sb + S_Z + (mg * 32 + lrow16) * ZS + lkhalf * 2;
    const uint32_t aZ1 = aZ0 + 16 * ZS;
    const uint32_t aH0 = sb + S_H + (mg * 32 + lrow16) * HS + lkhalf * 2;
    const uint32_t aH1 = aH0 + 16 * HS;
    // GEMM1 B (W1, n8): x2 ldmatrix, lanes 0-15 carry addresses
    const uint32_t bW1rel = (ng * 8 + (lane & 7)) * ZS + (((lane >> 3) & 1) << 4);
    // GEMM2 B (W2, 4 n-groups of 16)
    uint32_t bW2rel[4];
    #pragma unroll
    for (int t = 0; t < 4; t++)
        bW2rel[t] = (ng * 64 + t * 16 + brow) * W2S + bkhalf * 2;

    float dz[2][8][4];
    #pragma unroll
    for (int a = 0; a < 2; a++)
        #pragma unroll
        for (int b = 0; b < 8; b++)
            #pragma unroll
            for (int c = 0; c < 4; c++) dz[a][b][c] = 0.0f;
    float tr4[4] = {0.f, 0.f, 0.f, 0.f};

    for (int ch = 0; ch < NCHUNK; ch++) {
        const int jc  = ch * CW;
        const int buf = ch & 1;
        const uint32_t w1b = sb + S_W1 + buf * W1BUF + bW1rel;
        const uint32_t w2b = sb + S_W2 + buf * W2BUF;

        // prefetch next chunk's weights into the other buffer (overlaps everything)
        if (ch + 1 < NCHUNK) {
            cp_w1(sb, buf ^ 1, jc + CW);
            cp_w2(sb, buf ^ 1, jc + CW);
            CP_COMMIT();
        }

        // ---------------- GEMM1: pre[64x32] = z @ W1chunk^T (3 terms) --------
        float pre[2][4];
        #pragma unroll
        for (int a = 0; a < 2; a++)
            #pragma unroll
            for (int c = 0; c < 4; c++) pre[a][c] = 0.0f;

        #pragma unroll 4
        for (int ks = 0; ks < 16; ks++) {
            const int kb = ks * 32;
            uint32_t ah0[4], ah1[4], al0[4], al1[4], bh[2], bl[2];
            LDSM4(ah0, aZ0 + kb);
            LDSM4(ah1, aZ1 + kb);
            LDSM4(al0, aZ0 + kb + DLO_Z);
            LDSM4(al1, aZ1 + kb + DLO_Z);
            LDSM2(bh,  w1b + kb);
            LDSM2(bl,  w1b + kb + DLO_W1);
            mma_bf16(pre[0], ah0, bh[0], bh[1]);
            mma_bf16(pre[1], ah1, bh[0], bh[1]);
            mma_bf16(pre[0], al0, bh[0], bh[1]);
            mma_bf16(pre[1], al1, bh[0], bh[1]);
            mma_bf16(pre[0], ah0, bl[0], bl[1]);
            mma_bf16(pre[1], ah1, bl[0], bl[1]);
        }

        // ---------------- epilogue: softplus -> h (hi/lo), sigmoid*M ---------
        {
            const int j0 = jc + ng * 8 + 2 * (lane & 3);
            const float b10 = __ldg(&b1[j0]), b11 = __ldg(&b1[j0 + 1]);
            const float M0 = g_M[j0], M1 = g_M[j0 + 1];
            #pragma unroll
            for (int mf = 0; mf < 2; mf++) {
                #pragma unroll
                for (int bq = 0; bq < 2; bq++) {
                    float x0 = pre[mf][2 * bq]     + b10;
                    float x1 = pre[mf][2 * bq + 1] + b11;
                    float e0 = __expf(-fabsf(x0)), e1 = __expf(-fabsf(x1));
                    float sp0 = fmaxf(x0, 0.0f) + __logf(1.0f + e0);
                    float sp1 = fmaxf(x1, 0.0f) + __logf(1.0f + e1);
                    float i0 = __fdividef(1.0f, 1.0f + e0);
                    float i1 = __fdividef(1.0f, 1.0f + e1);
                    float sg0 = (x0 >= 0.0f) ? i0 : e0 * i0;
                    float sg1 = (x1 >= 0.0f) ? i1 : e1 * i1;
                    tr4[mf * 2 + bq] = fmaf(sg0, M0, tr4[mf * 2 + bq]);
                    tr4[mf * 2 + bq] = fmaf(sg1, M1, tr4[mf * 2 + bq]);
                    __nv_bfloat16 h0 = __float2bfloat16_rn(sp0);
                    __nv_bfloat16 h1 = __float2bfloat16_rn(sp1);
                    uint32_t phi = ((uint32_t)__bfloat16_as_ushort(h1) << 16) |
                                   (uint32_t)__bfloat16_as_ushort(h0);
                    __nv_bfloat16 l0 = __float2bfloat16_rn(sp0 - __bfloat162float(h0));
                    __nv_bfloat16 l1 = __float2bfloat16_rn(sp1 - __bfloat162float(h1));
                    uint32_t plo = ((uint32_t)__bfloat16_as_ushort(l1) << 16) |
                                   (uint32_t)__bfloat16_as_ushort(l0);
                    const int rl = mg * 32 + mf * 16 + (lane >> 2) + 8 * bq;
                    const int cl = ng * 8 + 2 * (lane & 3);
                    const uint32_t ha = sb + S_H + rl * HS + cl * 2;
                    asm volatile("st.shared.b32 [%0], %1;" :: "r"(ha), "r"(phi) : "memory");
                    asm volatile("st.shared.b32 [%0], %1;" :: "r"(ha + DLO_H), "r"(plo) : "memory");
                }
            }
        }
        __syncthreads();   // h fully written before any warp reads it

        // ---------------- GEMM2: dz[64x256] += h @ W2chunk (3 terms) ---------
        #pragma unroll
        for (int ks = 0; ks < 2; ks++) {
            const int kb = ks * 32;
            uint32_t ah0[4], ah1[4], al0[4], al1[4];
            LDSM4(ah0, aH0 + kb);
            LDSM4(ah1, aH1 + kb);
            LDSM4(al0, aH0 + kb + DLO_H);
            LDSM4(al1, aH1 + kb + DLO_H);
            #pragma unroll
            for (int t = 0; t < 4; t++) {
                uint32_t bh[4], bl[4];
                LDSM4(bh, w2b + bW2rel[t] + kb);
                LDSM4(bl, w2b + bW2rel[t] + kb + DLO_W2);
                mma_bf16(dz[0][2 * t],     ah0, bh[0], bh[1]);
                mma_bf16(dz[0][2 * t + 1], ah0, bh[2], bh[3]);
                mma_bf16(dz[1][2 * t],     ah1, bh[0], bh[1]);
                mma_bf16(dz[1][2 * t + 1], ah1, bh[2], bh[3]);
                mma_bf16(dz[0][2 * t],     al0, bh[0], bh[1]);
                mma_bf16(dz[0][2 * t + 1], al0, bh[2], bh[3]);
                mma_bf16(dz[1][2 * t],     al1, bh[0], bh[1]);
                mma_bf16(dz[1][2 * t + 1], al1, bh[2], bh[3]);
                mma_bf16(dz[0][2 * t],     ah0, bl[0], bl[1]);
                mma_bf16(dz[0][2 * t + 1], ah0, bl[2], bl[3]);
                mma_bf16(dz[1][2 * t],     ah1, bl[0], bl[1]);
                mma_bf16(dz[1][2 * t + 1], ah1, bl[2], bl[3]);
            }
        }

        // wait for next chunk's weights, then release h + switch buffers
        if (ch + 1 < NCHUNK) CP_WAIT0();
        __syncthreads();
    }

    // ---------------- writeout ----------------
    #pragma unroll
    for (int mf = 0; mf < 2; mf++) {
        const int rl = mg * 32 + mf * 16 + (lane >> 2);
        #pragma unroll
        for (int nf = 0; nf < 8; nf++) {
            const int col = ng * 64 + nf * 8 + 2 * (lane & 3);
            float2 v0 = make_float2(dz[mf][nf][0], dz[mf][nf][1]);
            float2 v1 = make_float2(dz[mf][nf][2], dz[mf][nf][3]);
            *reinterpret_cast<float2*>(dz_out + (size_t)(row0 + rl) * D_DIM + col) = v0;
            *reinterpret_cast<float2*>(dz_out + (size_t)(row0 + rl + 8) * D_DIM + col) = v1;
        }
    }
    #pragma unroll
    for (int i = 0; i < 4; i++) {
        const int rl = mg * 32 + (i >> 1) * 16 + (lane >> 2) + 8 * (i & 1);
        atomicAdd(&sTr[rl], tr4[i]);
    }
    __syncthreads();
    if (tid < MTILE) dlog_out[row0 + tid] = -sTr[tid];
}

// ---------------------------------------------------------------------------
extern "C" void kernel_launch(void* const* d_in, const int* in_sizes, int n_in,
                              void* d_out, int out_size) {
    const float* z  = (const float*)d_in[1];
    const float* W1 = (const float*)d_in[2];
    const float* b1 = (const float*)d_in[3];
    const float* W2 = (const float*)d_in[4];

    float* dz   = (float*)d_out;
    float* dlog = dz + (size_t)BATCH * D_DIM;

    __nv_bfloat16 *zhi, *zlo, *w1hi, *w1lo, *w2hi, *w2lo;
    cudaGetSymbolAddress((void**)&zhi,  g_z_hi);
    cudaGetSymbolAddress((void**)&zlo,  g_z_lo);
    cudaGetSymbolAddress((void**)&w1hi, g_w1_hi);
    cudaGetSymbolAddress((void**)&w1lo, g_w1_lo);
    cudaGetSymbolAddress((void**)&w2hi, g_w2_hi);
    cudaGetSymbolAddress((void**)&w2lo, g_w2_lo);

    split_kernel<<<(int)((size_t)BATCH * D_DIM / 8 / 256), 256>>>(z, zhi, zlo);
    split_kernel<<<(W_DIM * D_DIM / 8) / 256, 256>>>(W1, w1hi, w1lo);
    split_kernel<<<(D_DIM * W_DIM / 8) / 256, 256>>>(W2, w2hi, w2lo);
    compute_M_kernel<<<W_DIM, 256>>>(W1, W2);

    cudaFuncSetAttribute(planar_mma_kernel,
                         cudaFuncAttributeMaxDynamicSharedMemorySize, S_TOTAL);
    planar_mma_kernel<<<BATCH / MTILE, 256, S_TOTAL>>>(b1, dz, dlog);
}

// round 6
// speedup vs baseline: 1.2292x; 1.2292x over previous
#include <cuda_runtime.h>
#include <cuda_bf16.h>
#include <stdint.h>
#include <math.h>

#define BATCH  65536
#define D_DIM  256
#define W_DIM  1024
#define MTILE  64
#define CW     64
#define NCHUNK (W_DIM / CW)    // 16

// bf16 hi/lo split images (natural row-major) in device scratch
__device__ __align__(16) __nv_bfloat16 g_z_hi[(size_t)BATCH * D_DIM];
__device__ __align__(16) __nv_bfloat16 g_z_lo[(size_t)BATCH * D_DIM];
__device__ __align__(16) __nv_bfloat16 g_w1_hi[W_DIM * D_DIM];
__device__ __align__(16) __nv_bfloat16 g_w1_lo[W_DIM * D_DIM];
__device__ __align__(16) __nv_bfloat16 g_w2_hi[D_DIM * W_DIM];
__device__ __align__(16) __nv_bfloat16 g_w2_lo[D_DIM * W_DIM];
__device__ float g_M[W_DIM];

// ---------------- SMEM layout (bytes) ----------------
// z  : [64][264] bf16, stride 528B (conflict-free ldmatrix)
// W1 : [64][264] bf16 (chunk, rows = W-col j, cols = k)
// W2 : [256][72] bf16, stride 144B (rows = out i, cols = chunk j)
// h  : [64][72]  bf16
#define Z_HI   0
#define Z_LO   33792
#define W1_HI  67584
#define W1_LO  101376
#define W2_HI  135168
#define W2_LO  172032
#define H_HI   208896
#define H_LO   218112
#define TR_OFF 227328
#define S_TOTAL 227584

#define ZS  528
#define W2S 144
#define HS  144
#define DLO 33792      // hi->lo offset for z / W1
#define DW2 36864      // hi->lo offset for W2
#define DH  9216       // hi->lo offset for h

// ---------------- PTX helpers ----------------
__device__ __forceinline__ uint32_t smem_u32(const void* p) {
    uint32_t a;
    asm("{ .reg .u64 t; cvta.to.shared.u64 t, %1; cvt.u32.u64 %0, t; }" : "=r"(a) : "l"(p));
    return a;
}
#define CP_ASYNC16(d, s) \
    asm volatile("cp.async.cg.shared.global [%0], [%1], 16;" :: "r"(d), "l"(s))
#define CP_COMMIT() asm volatile("cp.async.commit_group;")
#define CP_WAIT0()  asm volatile("cp.async.wait_group 0;")
#define CP_WAIT1()  asm volatile("cp.async.wait_group 1;")

#define LDSM4(r, addr) \
    asm volatile("ldmatrix.sync.aligned.m8n8.x4.shared.b16 {%0,%1,%2,%3}, [%4];" \
        : "=r"((r)[0]), "=r"((r)[1]), "=r"((r)[2]), "=r"((r)[3]) : "r"(addr))

__device__ __forceinline__ void mma_bf16(float* c, const uint32_t* a, uint32_t b0, uint32_t b1) {
    asm volatile(
        "mma.sync.aligned.m16n8k16.row.col.f32.bf16.bf16.f32 "
        "{%0,%1,%2,%3}, {%4,%5,%6,%7}, {%8,%9}, {%0,%1,%2,%3};"
        : "+f"(c[0]), "+f"(c[1]), "+f"(c[2]), "+f"(c[3])
        : "r"(a[0]), "r"(a[1]), "r"(a[2]), "r"(a[3]), "r"(b0), "r"(b1));
}

// ---------------- split pre-pass ----------------
union Pack8 { uint4 u; __nv_bfloat16 b[8]; };

__global__ void split_kernel(const float* __restrict__ src,
                             __nv_bfloat16* __restrict__ dhi,
                             __nv_bfloat16* __restrict__ dlo) {
    size_t gid = (size_t)blockIdx.x * 256 + threadIdx.x;
    const float4* s = reinterpret_cast<const float4*>(src);
    float4 a = s[gid * 2], b = s[gid * 2 + 1];
    float v[8] = {a.x, a.y, a.z, a.w, b.x, b.y, b.z, b.w};
    Pack8 hi, lo;
    #pragma unroll
    for (int i = 0; i < 8; i++) {
        __nv_bfloat16 h = __float2bfloat16_rn(v[i]);
        hi.b[i] = h;
        lo.b[i] = __float2bfloat16_rn(v[i] - __bfloat162float(h));
    }
    reinterpret_cast<uint4*>(dhi)[gid] = hi.u;
    reinterpret_cast<uint4*>(dlo)[gid] = lo.u;
}

__global__ void compute_M_kernel(const float* __restrict__ W1, const float* __restrict__ W2) {
    int j = blockIdx.x, i = threadIdx.x;
    float v = W1[j * D_DIM + i] * W2[(size_t)i * W_DIM + j];
    #pragma unroll
    for (int o = 16; o > 0; o >>= 1) v += __shfl_down_sync(0xffffffffu, v, o);
    __shared__ float red[8];
    if ((i & 31) == 0) red[i >> 5] = v;
    __syncthreads();
    if (i < 8) {
        float s = red[i];
        #pragma unroll
        for (int o = 4; o > 0; o >>= 1) s += __shfl_down_sync(0xffu, s, o);
        if (i == 0) g_M[j] = s;
    }
}

// ---------------- copy helpers (cp.async) ----------------
// rows x 256 bf16 from natural layout -> smem stride 528B
__device__ __forceinline__ void cp_tile256(uint32_t sdst, const __nv_bfloat16* g, int rows) {
    int total = rows * 32;
    for (int i = threadIdx.x; i < total; i += 256) {
        int r = i >> 5, c = i & 31;
        CP_ASYNC16(sdst + r * ZS + c * 16, g + r * 256 + c * 8);
    }
}
// 256 rows x 64 bf16 from stride-1024 rows -> smem stride 144B
__device__ __forceinline__ void cp_tileW2(uint32_t sdst, const __nv_bfloat16* g) {
    for (int i = threadIdx.x; i < 256 * 8; i += 256) {
        int r = i >> 3, c = i & 7;
        CP_ASYNC16(sdst + r * W2S + c * 16, g + (size_t)r * W_DIM + c * 8);
    }
}

// ---------------- main fused kernel ----------------
__global__ void __launch_bounds__(256, 1)
planar_mma_kernel(const float* __restrict__ b1,
                  float* __restrict__ dz_out,
                  float* __restrict__ dlog_out) {
    extern __shared__ char smem[];
    const uint32_t sb = smem_u32(smem);
    float* sTr = reinterpret_cast<float*>(smem + TR_OFF);

    const int tid  = threadIdx.x;
    const int wid  = tid >> 5;
    const int lane = tid & 31;
    const int mg   = wid >> 2;     // 0/1 : rows 32*mg .. +31
    const int ng   = wid & 3;      // GEMM1 n-group (16 cols), GEMM2 n-group (64 cols)
    const int row0 = blockIdx.x * MTILE;

    if (tid < MTILE) sTr[tid] = 0.0f;

    // prologue: z (hi+lo) + chunk-0 weights, single group, full wait
    cp_tile256(sb + Z_HI, g_z_hi + (size_t)row0 * D_DIM, 64);
    cp_tile256(sb + Z_LO, g_z_lo + (size_t)row0 * D_DIM, 64);
    cp_tile256(sb + W1_HI, g_w1_hi, 64);
    cp_tile256(sb + W1_LO, g_w1_lo, 64);
    cp_tileW2(sb + W2_HI, g_w2_hi);
    cp_tileW2(sb + W2_LO, g_w2_lo);
    CP_COMMIT();
    CP_WAIT0();
    __syncthreads();

    // per-lane ldmatrix base addresses
    const int lrow16 = lane & 15;          // A-frag row within 16
    const int lkhalf = (lane >> 4) << 3;   // A-frag k half (0/8)
    const int brow   = (lane & 7) + ((lane >> 4) << 3);   // B-frag row within 16
    const int bkhalf = ((lane >> 3) & 1) << 3;            // B-frag k half

    const uint32_t aZ0 = sb + Z_HI + (mg * 32 + lrow16) * ZS + lkhalf * 2;
    const uint32_t aZ1 = aZ0 + 16 * ZS;
    const uint32_t bW1 = sb + W1_HI + (ng * 16 + brow) * ZS + bkhalf * 2;
    const uint32_t aH0 = sb + H_HI + (mg * 32 + lrow16) * HS + lkhalf * 2;
    const uint32_t aH1 = aH0 + 16 * HS;
    uint32_t bW2[4];
    #pragma unroll
    for (int t = 0; t < 4; t++)
        bW2[t] = sb + W2_HI + (ng * 64 + t * 16 + brow) * W2S + bkhalf * 2;

    float dz[2][8][4];
    #pragma unroll
    for (int a = 0; a < 2; a++)
        #pragma unroll
        for (int b = 0; b < 8; b++)
            #pragma unroll
            for (int c = 0; c < 4; c++) dz[a][b][c] = 0.0f;
    float tr4[4] = {0.f, 0.f, 0.f, 0.f};

    for (int ch = 0; ch < NCHUNK; ch++) {
        const int jc = ch * CW;

        // ---------------- GEMM1: pre[64x64] = z @ W1chunk^T (3 bf16 terms) ----
        float pre[2][2][4];
        #pragma unroll
        for (int a = 0; a < 2; a++)
            #pragma unroll
            for (int b = 0; b < 2; b++)
                #pragma unroll
                for (int c = 0; c < 4; c++) pre[a][b][c] = 0.0f;

        #pragma unroll 4
        for (int ks = 0; ks < 16; ks++) {
            const int kb = ks * 32;
            uint32_t ah0[4], ah1[4], al0[4], al1[4], bh[4], bl[4];
            LDSM4(ah0, aZ0 + kb);
            LDSM4(ah1, aZ1 + kb);
            LDSM4(al0, aZ0 + kb + DLO);
            LDSM4(al1, aZ1 + kb + DLO);
            LDSM4(bh,  bW1 + kb);
            LDSM4(bl,  bW1 + kb + DLO);
            // hi*hi
            mma_bf16(pre[0][0], ah0, bh[0], bh[1]);
            mma_bf16(pre[0][1], ah0, bh[2], bh[3]);
            mma_bf16(pre[1][0], ah1, bh[0], bh[1]);
            mma_bf16(pre[1][1], ah1, bh[2], bh[3]);
            // lo*hi
            mma_bf16(pre[0][0], al0, bh[0], bh[1]);
            mma_bf16(pre[0][1], al0, bh[2], bh[3]);
            mma_bf16(pre[1][0], al1, bh[0], bh[1]);
            mma_bf16(pre[1][1], al1, bh[2], bh[3]);
            // hi*lo
            mma_bf16(pre[0][0], ah0, bl[0], bl[1]);
            mma_bf16(pre[0][1], ah0, bl[2], bl[3]);
            mma_bf16(pre[1][0], ah1, bl[0], bl[1]);
            mma_bf16(pre[1][1], ah1, bl[2], bl[3]);
        }

        // ---------------- epilogue: softplus -> h (hi/lo), sigmoid*M -> trace --
        // h buffer is safe to write: its last readers (GEMM2 of ch-1) finished
        // before the sync at the tail of the previous iteration.
        #pragma unroll
        for (int mf = 0; mf < 2; mf++) {
            #pragma unroll
            for (int nf = 0; nf < 2; nf++) {
                const int j0 = jc + ng * 16 + nf * 8 + 2 * (lane & 3);
                const float b10 = __ldg(&b1[j0]),   b11 = __ldg(&b1[j0 + 1]);
                const float M0  = g_M[j0],          M1  = g_M[j0 + 1];
                #pragma unroll
                for (int bq = 0; bq < 2; bq++) {
                    float x0 = pre[mf][nf][2 * bq]     + b10;
                    float x1 = pre[mf][nf][2 * bq + 1] + b11;
                    float e0 = __expf(-fabsf(x0)), e1 = __expf(-fabsf(x1));
                    float sp0 = fmaxf(x0, 0.0f) + __logf(1.0f + e0);
                    float sp1 = fmaxf(x1, 0.0f) + __logf(1.0f + e1);
                    float i0 = __fdividef(1.0f, 1.0f + e0);
                    float i1 = __fdividef(1.0f, 1.0f + e1);
                    float sg0 = (x0 >= 0.0f) ? i0 : e0 * i0;
                    float sg1 = (x1 >= 0.0f) ? i1 : e1 * i1;
                    tr4[mf * 2 + bq] = fmaf(sg0, M0, tr4[mf * 2 + bq]);
                    tr4[mf * 2 + bq] = fmaf(sg1, M1, tr4[mf * 2 + bq]);
                    __nv_bfloat16 h0 = __float2bfloat16_rn(sp0);
                    __nv_bfloat16 h1 = __float2bfloat16_rn(sp1);
                    uint32_t phi = ((uint32_t)__bfloat16_as_ushort(h1) << 16) |
                                   (uint32_t)__bfloat16_as_ushort(h0);
                    __nv_bfloat16 l0 = __float2bfloat16_rn(sp0 - __bfloat162float(h0));
                    __nv_bfloat16 l1 = __float2bfloat16_rn(sp1 - __bfloat162float(h1));
                    uint32_t plo = ((uint32_t)__bfloat16_as_ushort(l1) << 16) |
                                   (uint32_t)__bfloat16_as_ushort(l0);
                    const int rl = mg * 32 + mf * 16 + (lane >> 2) + 8 * bq;
                    const int cl = ng * 16 + nf * 8 + 2 * (lane & 3);
                    const uint32_t ha = sb + H_HI + rl * HS + cl * 2;
                    asm volatile("st.shared.b32 [%0], %1;" :: "r"(ha), "r"(phi) : "memory");
                    asm volatile("st.shared.b32 [%0], %1;" :: "r"(ha + DH), "r"(plo) : "memory");
                }
            }
        }

        __syncthreads();   // A: all warps past GEMM1 -> W1 buffer free

        // issue W1(ch+1): hidden under GEMM2(ch)
        if (ch + 1 < NCHUNK) {
            cp_tile256(sb + W1_HI, g_w1_hi + (size_t)(jc + CW) * D_DIM, 64);
            cp_tile256(sb + W1_LO, g_w1_lo + (size_t)(jc + CW) * D_DIM, 64);
            CP_COMMIT();
        }

        // W2(ch) was issued at the tail of iteration ch-1; wait for it now,
        // leaving the just-issued W1(ch+1) group in flight.
        if (ch > 0) {
            if (ch + 1 < NCHUNK) CP_WAIT1(); else CP_WAIT0();
        }
        __syncthreads();   // B: h + W2(ch) visible to all warps

        // ---------------- GEMM2: dz[64x256] += h @ W2chunk (3 bf16 terms) -----
        #pragma unroll
        for (int ks = 0; ks < 4; ks++) {
            const int kb = ks * 32;
            uint32_t ah0[4], ah1[4], al0[4], al1[4];
            LDSM4(ah0, aH0 + kb);
            LDSM4(ah1, aH1 + kb);
            LDSM4(al0, aH0 + kb + DH);
            LDSM4(al1, aH1 + kb + DH);
            #pragma unroll
            for (int t = 0; t < 4; t++) {
                uint32_t bh[4], bl[4];
                LDSM4(bh, bW2[t] + kb);
                LDSM4(bl, bW2[t] + kb + DW2);
                // hi*hi
                mma_bf16(dz[0][2 * t],     ah0, bh[0], bh[1]);
                mma_bf16(dz[0][2 * t + 1], ah0, bh[2], bh[3]);
                mma_bf16(dz[1][2 * t],     ah1, bh[0], bh[1]);
                mma_bf16(dz[1][2 * t + 1], ah1, bh[2], bh[3]);
                // lo*hi
                mma_bf16(dz[0][2 * t],     al0, bh[0], bh[1]);
                mma_bf16(dz[0][2 * t + 1], al0, bh[2], bh[3]);
                mma_bf16(dz[1][2 * t],     al1, bh[0], bh[1]);
                mma_bf16(dz[1][2 * t + 1], al1, bh[2], bh[3]);
                // hi*lo
                mma_bf16(dz[0][2 * t],     ah0, bl[0], bl[1]);
                mma_bf16(dz[0][2 * t + 1], ah0, bl[2], bl[3]);
                mma_bf16(dz[1][2 * t],     ah1, bl[0], bl[1]);
                mma_bf16(dz[1][2 * t + 1], ah1, bl[2], bl[3]);
            }
        }

        __syncthreads();   // C: all warps past GEMM2 -> W2 buffer free

        // issue W2(ch+1): stays in flight across the chunk boundary, hidden
        // under GEMM1(ch+1) + epilogue; wait for W1(ch+1) before next GEMM1.
        if (ch + 1 < NCHUNK) {
            cp_tileW2(sb + W2_HI, g_w2_hi + jc + CW);
            cp_tileW2(sb + W2_LO, g_w2_lo + jc + CW);
            CP_COMMIT();
            CP_WAIT1();        // W1(ch+1) done; W2(ch+1) still in flight
            __syncthreads();   // D: W1(ch+1) visible to all warps
        }
    }

    // ---------------- writeout ----------------
    #pragma unroll
    for (int mf = 0; mf < 2; mf++) {
        const int rl = mg * 32 + mf * 16 + (lane >> 2);
        #pragma unroll
        for (int nf = 0; nf < 8; nf++) {
            const int col = ng * 64 + nf * 8 + 2 * (lane & 3);
            float2 v0 = make_float2(dz[mf][nf][0], dz[mf][nf][1]);
            float2 v1 = make_float2(dz[mf][nf][2], dz[mf][nf][3]);
            *reinterpret_cast<float2*>(dz_out + (size_t)(row0 + rl) * D_DIM + col) = v0;
            *reinterpret_cast<float2*>(dz_out + (size_t)(row0 + rl + 8) * D_DIM + col) = v1;
        }
    }
    #pragma unroll
    for (int i = 0; i < 4; i++) {
        const int rl = mg * 32 + (i >> 1) * 16 + (lane >> 2) + 8 * (i & 1);
        atomicAdd(&sTr[rl], tr4[i]);
    }
    __syncthreads();
    if (tid < MTILE) dlog_out[row0 + tid] = -sTr[tid];
}

// ---------------------------------------------------------------------------
extern "C" void kernel_launch(void* const* d_in, const int* in_sizes, int n_in,
                              void* d_out, int out_size) {
    const float* z  = (const float*)d_in[1];
    const float* W1 = (const float*)d_in[2];
    const float* b1 = (const float*)d_in[3];
    const float* W2 = (const float*)d_in[4];

    float* dz   = (float*)d_out;
    float* dlog = dz + (size_t)BATCH * D_DIM;

    __nv_bfloat16 *zhi, *zlo, *w1hi, *w1lo, *w2hi, *w2lo;
    cudaGetSymbolAddress((void**)&zhi,  g_z_hi);
    cudaGetSymbolAddress((void**)&zlo,  g_z_lo);
    cudaGetSymbolAddress((void**)&w1hi, g_w1_hi);
    cudaGetSymbolAddress((void**)&w1lo, g_w1_lo);
    cudaGetSymbolAddress((void**)&w2hi, g_w2_hi);
    cudaGetSymbolAddress((void**)&w2lo, g_w2_lo);

    split_kernel<<<(int)((size_t)BATCH * D_DIM / 8 / 256), 256>>>(z, zhi, zlo);
    split_kernel<<<(W_DIM * D_DIM / 8) / 256, 256>>>(W1, w1hi, w1lo);
    split_kernel<<<(D_DIM * W_DIM / 8) / 256, 256>>>(W2, w2hi, w2lo);
    compute_M_kernel<<<W_DIM, 256>>>(W1, W2);

    cudaFuncSetAttribute(planar_mma_kernel,
                         cudaFuncAttributeMaxDynamicSharedMemorySize, S_TOTAL);
    planar_mma_kernel<<<BATCH / MTILE, 256, S_TOTAL>>>(b1, dz, dlog);
}

// round 7
// speedup vs baseline: 1.6563x; 1.3474x over previous
#include <cuda_runtime.h>
#include <cuda_fp16.h>
#include <stdint.h>
#include <math.h>

#define BATCH  65536
#define D_DIM  256
#define W_DIM  1024
#define MTILE  64
#define CW     64
#define NCHUNK (W_DIM / CW)    // 16
#define WSCALE 64.0f
#define WINV   (1.0f / 64.0f)

// device scratch: z split fp16 hi/lo; weights single scaled fp16
__device__ __align__(16) __half g_z_hi[(size_t)BATCH * D_DIM];
__device__ __align__(16) __half g_z_lo[(size_t)BATCH * D_DIM];
__device__ __align__(16) __half g_w1s[W_DIM * D_DIM];   // W1 * 64
__device__ __align__(16) __half g_w2s[D_DIM * W_DIM];   // W2 * 64
__device__ float g_M[W_DIM];

// ---------------- SMEM layout (bytes) ----------------
// z  : [64][264] fp16 hi + lo, stride 528B
// W1 : [64][264] fp16 (chunk, rows = W-col j, cols = k)
// W2 : [256][72] fp16, stride 144B
// h  : [64][72]  fp16 hi + lo
#define Z_HI   0
#define Z_LO   33792
#define W1_S   67584
#define W2_S   101376
#define H_HI   138240
#define H_LO   147456
#define TR_OFF 156672
#define S_TOTAL 156928

#define ZS  528
#define W2S 144
#define HS  144
#define DLO_Z 33792
#define DH    9216

// ---------------- PTX helpers ----------------
__device__ __forceinline__ uint32_t smem_u32(const void* p) {
    uint32_t a;
    asm("{ .reg .u64 t; cvta.to.shared.u64 t, %1; cvt.u32.u64 %0, t; }" : "=r"(a) : "l"(p));
    return a;
}
#define CP_ASYNC16(d, s) \
    asm volatile("cp.async.cg.shared.global [%0], [%1], 16;" :: "r"(d), "l"(s))
#define CP_COMMIT() asm volatile("cp.async.commit_group;")
#define CP_WAIT0()  asm volatile("cp.async.wait_group 0;")
#define CP_WAIT1()  asm volatile("cp.async.wait_group 1;")

#define LDSM4(r, addr) \
    asm volatile("ldmatrix.sync.aligned.m8n8.x4.shared.b16 {%0,%1,%2,%3}, [%4];" \
        : "=r"((r)[0]), "=r"((r)[1]), "=r"((r)[2]), "=r"((r)[3]) : "r"(addr))

__device__ __forceinline__ void mma_f16(float* c, const uint32_t* a, uint32_t b0, uint32_t b1) {
    asm volatile(
        "mma.sync.aligned.m16n8k16.row.col.f32.f16.f16.f32 "
        "{%0,%1,%2,%3}, {%4,%5,%6,%7}, {%8,%9}, {%0,%1,%2,%3};"
        : "+f"(c[0]), "+f"(c[1]), "+f"(c[2]), "+f"(c[3])
        : "r"(a[0]), "r"(a[1]), "r"(a[2]), "r"(a[3]), "r"(b0), "r"(b1));
}

// ---------------- pre-pass kernels ----------------
union PackH8 { uint4 u; __half h[8]; };

__global__ void split_z_kernel(const float* __restrict__ src,
                               __half* __restrict__ dhi,
                               __half* __restrict__ dlo) {
    size_t gid = (size_t)blockIdx.x * 256 + threadIdx.x;
    const float4* s = reinterpret_cast<const float4*>(src);
    float4 a = s[gid * 2], b = s[gid * 2 + 1];
    float v[8] = {a.x, a.y, a.z, a.w, b.x, b.y, b.z, b.w};
    PackH8 hi, lo;
    #pragma unroll
    for (int i = 0; i < 8; i++) {
        __half h = __float2half_rn(v[i]);
        hi.h[i] = h;
        lo.h[i] = __float2half_rn(v[i] - __half2float(h));
    }
    reinterpret_cast<uint4*>(dhi)[gid] = hi.u;
    reinterpret_cast<uint4*>(dlo)[gid] = lo.u;
}

__global__ void conv_w_kernel(const float* __restrict__ src,
                              __half* __restrict__ dst) {
    size_t gid = (size_t)blockIdx.x * 256 + threadIdx.x;
    const float4* s = reinterpret_cast<const float4*>(src);
    float4 a = s[gid * 2], b = s[gid * 2 + 1];
    float v[8] = {a.x, a.y, a.z, a.w, b.x, b.y, b.z, b.w};
    PackH8 o;
    #pragma unroll
    for (int i = 0; i < 8; i++) o.h[i] = __float2half_rn(v[i] * WSCALE);
    reinterpret_cast<uint4*>(dst)[gid] = o.u;
}

__global__ void compute_M_kernel(const float* __restrict__ W1, const float* __restrict__ W2) {
    int j = blockIdx.x, i = threadIdx.x;
    float v = W1[j * D_DIM + i] * W2[(size_t)i * W_DIM + j];
    #pragma unroll
    for (int o = 16; o > 0; o >>= 1) v += __shfl_down_sync(0xffffffffu, v, o);
    __shared__ float red[8];
    if ((i & 31) == 0) red[i >> 5] = v;
    __syncthreads();
    if (i < 8) {
        float s = red[i];
        #pragma unroll
        for (int o = 4; o > 0; o >>= 1) s += __shfl_down_sync(0xffu, s, o);
        if (i == 0) g_M[j] = s;
    }
}

// ---------------- copy helpers (cp.async) ----------------
__device__ __forceinline__ void cp_tile256(uint32_t sdst, const __half* g, int rows) {
    int total = rows * 32;
    for (int i = threadIdx.x; i < total; i += 256) {
        int r = i >> 5, c = i & 31;
        CP_ASYNC16(sdst + r * ZS + c * 16, g + r * 256 + c * 8);
    }
}
__device__ __forceinline__ void cp_tileW2(uint32_t sdst, const __half* g) {
    for (int i = threadIdx.x; i < 256 * 8; i += 256) {
        int r = i >> 3, c = i & 7;
        CP_ASYNC16(sdst + r * W2S + c * 16, g + (size_t)r * W_DIM + c * 8);
    }
}

// ---------------- main fused kernel ----------------
__global__ void __launch_bounds__(256, 1)
planar_mma_kernel(const float* __restrict__ b1,
                  float* __restrict__ dz_out,
                  float* __restrict__ dlog_out) {
    extern __shared__ char smem[];
    const uint32_t sb = smem_u32(smem);
    float* sTr = reinterpret_cast<float*>(smem + TR_OFF);

    const int tid  = threadIdx.x;
    const int wid  = tid >> 5;
    const int lane = tid & 31;
    const int mg   = wid >> 2;     // 0/1 : rows 32*mg .. +31
    const int ng   = wid & 3;      // GEMM1: 16 cols; GEMM2: 64 cols
    const int row0 = blockIdx.x * MTILE;

    if (tid < MTILE) sTr[tid] = 0.0f;

    // prologue: z (hi+lo) + chunk-0 weights
    cp_tile256(sb + Z_HI, g_z_hi + (size_t)row0 * D_DIM, 64);
    cp_tile256(sb + Z_LO, g_z_lo + (size_t)row0 * D_DIM, 64);
    cp_tile256(sb + W1_S, g_w1s, 64);
    cp_tileW2(sb + W2_S, g_w2s);
    CP_COMMIT();
    CP_WAIT0();
    __syncthreads();

    // per-lane ldmatrix base addresses
    const int lrow16 = lane & 15;
    const int lkhalf = (lane >> 4) << 3;
    const int brow   = (lane & 7) + ((lane >> 4) << 3);
    const int bkhalf = ((lane >> 3) & 1) << 3;

    const uint32_t aZ0 = sb + Z_HI + (mg * 32 + lrow16) * ZS + lkhalf * 2;
    const uint32_t aZ1 = aZ0 + 16 * ZS;
    const uint32_t bW1 = sb + W1_S + (ng * 16 + brow) * ZS + bkhalf * 2;
    const uint32_t aH0 = sb + H_HI + (mg * 32 + lrow16) * HS + lkhalf * 2;
    const uint32_t aH1 = aH0 + 16 * HS;
    uint32_t bW2[4];
    #pragma unroll
    for (int t = 0; t < 4; t++)
        bW2[t] = sb + W2_S + (ng * 64 + t * 16 + brow) * W2S + bkhalf * 2;

    float dz[2][8][4];
    #pragma unroll
    for (int a = 0; a < 2; a++)
        #pragma unroll
        for (int b = 0; b < 8; b++)
            #pragma unroll
            for (int c = 0; c < 4; c++) dz[a][b][c] = 0.0f;
    float tr4[4] = {0.f, 0.f, 0.f, 0.f};

    for (int ch = 0; ch < NCHUNK; ch++) {
        const int jc = ch * CW;

        // ---------- GEMM1: pre64 = z @ (64*W1chunk)^T (2 fp16 terms) ----------
        float pre[2][2][4];
        #pragma unroll
        for (int a = 0; a < 2; a++)
            #pragma unroll
            for (int b = 0; b < 2; b++)
                #pragma unroll
                for (int c = 0; c < 4; c++) pre[a][b][c] = 0.0f;

        #pragma unroll 4
        for (int ks = 0; ks < 16; ks++) {
            const int kb = ks * 32;
            uint32_t ah0[4], ah1[4], al0[4], al1[4], bh[4];
            LDSM4(ah0, aZ0 + kb);
            LDSM4(ah1, aZ1 + kb);
            LDSM4(al0, aZ0 + kb + DLO_Z);
            LDSM4(al1, aZ1 + kb + DLO_Z);
            LDSM4(bh,  bW1 + kb);
            // zh * w1
            mma_f16(pre[0][0], ah0, bh[0], bh[1]);
            mma_f16(pre[0][1], ah0, bh[2], bh[3]);
            mma_f16(pre[1][0], ah1, bh[0], bh[1]);
            mma_f16(pre[1][1], ah1, bh[2], bh[3]);
            // zl * w1
            mma_f16(pre[0][0], al0, bh[0], bh[1]);
            mma_f16(pre[0][1], al0, bh[2], bh[3]);
            mma_f16(pre[1][0], al1, bh[0], bh[1]);
            mma_f16(pre[1][1], al1, bh[2], bh[3]);
        }

        // ---------- epilogue: x = pre/64 + b1; softplus -> h hi/lo; trace -----
        #pragma unroll
        for (int mf = 0; mf < 2; mf++) {
            #pragma unroll
            for (int nf = 0; nf < 2; nf++) {
                const int j0 = jc + ng * 16 + nf * 8 + 2 * (lane & 3);
                const float b10 = __ldg(&b1[j0]),   b11 = __ldg(&b1[j0 + 1]);
                const float M0  = g_M[j0],          M1  = g_M[j0 + 1];
                #pragma unroll
                for (int bq = 0; bq < 2; bq++) {
                    float x0 = fmaf(pre[mf][nf][2 * bq],     WINV, b10);
                    float x1 = fmaf(pre[mf][nf][2 * bq + 1], WINV, b11);
                    float e0 = __expf(-fabsf(x0)), e1 = __expf(-fabsf(x1));
                    float sp0 = fmaxf(x0, 0.0f) + __logf(1.0f + e0);
                    float sp1 = fmaxf(x1, 0.0f) + __logf(1.0f + e1);
                    float i0 = __fdividef(1.0f, 1.0f + e0);
                    float i1 = __fdividef(1.0f, 1.0f + e1);
                    float sg0 = (x0 >= 0.0f) ? i0 : e0 * i0;
                    float sg1 = (x1 >= 0.0f) ? i1 : e1 * i1;
                    tr4[mf * 2 + bq] = fmaf(sg0, M0, tr4[mf * 2 + bq]);
                    tr4[mf * 2 + bq] = fmaf(sg1, M1, tr4[mf * 2 + bq]);
                    __half h0 = __float2half_rn(sp0);
                    __half h1 = __float2half_rn(sp1);
                    uint32_t phi = ((uint32_t)__half_as_ushort(h1) << 16) |
                                   (uint32_t)__half_as_ushort(h0);
                    __half l0 = __float2half_rn(sp0 - __half2float(h0));
                    __half l1 = __float2half_rn(sp1 - __half2float(h1));
                    uint32_t plo = ((uint32_t)__half_as_ushort(l1) << 16) |
                                   (uint32_t)__half_as_ushort(l0);
                    const int rl = mg * 32 + mf * 16 + (lane >> 2) + 8 * bq;
                    const int cl = ng * 16 + nf * 8 + 2 * (lane & 3);
                    const uint32_t ha = sb + H_HI + rl * HS + cl * 2;
                    asm volatile("st.shared.b32 [%0], %1;" :: "r"(ha), "r"(phi) : "memory");
                    asm volatile("st.shared.b32 [%0], %1;" :: "r"(ha + DH), "r"(plo) : "memory");
                }
            }
        }

        __syncthreads();   // A: all warps past GEMM1 -> W1 buffer free

        // issue W1(ch+1): hidden under GEMM2(ch)
        if (ch + 1 < NCHUNK) {
            cp_tile256(sb + W1_S, g_w1s + (size_t)(jc + CW) * D_DIM, 64);
            CP_COMMIT();
        }
        // wait for W2(ch) (issued at tail of ch-1), leave W1(ch+1) in flight
        if (ch > 0) {
            if (ch + 1 < NCHUNK) CP_WAIT1(); else CP_WAIT0();
        }
        __syncthreads();   // B: h + W2(ch) visible

        // ---------- GEMM2: dz64 += h @ (64*W2chunk) (2 fp16 terms) ------------
        #pragma unroll
        for (int ks = 0; ks < 4; ks++) {
            const int kb = ks * 32;
            uint32_t ah0[4], ah1[4], al0[4], al1[4];
            LDSM4(ah0, aH0 + kb);
            LDSM4(ah1, aH1 + kb);
            LDSM4(al0, aH0 + kb + DH);
            LDSM4(al1, aH1 + kb + DH);
            #pragma unroll
            for (int t = 0; t < 4; t++) {
                uint32_t bh[4];
                LDSM4(bh, bW2[t] + kb);
                // hh * w2
                mma_f16(dz[0][2 * t],     ah0, bh[0], bh[1]);
                mma_f16(dz[0][2 * t + 1], ah0, bh[2], bh[3]);
                mma_f16(dz[1][2 * t],     ah1, bh[0], bh[1]);
                mma_f16(dz[1][2 * t + 1], ah1, bh[2], bh[3]);
                // hl * w2
                mma_f16(dz[0][2 * t],     al0, bh[0], bh[1]);
                mma_f16(dz[0][2 * t + 1], al0, bh[2], bh[3]);
                mma_f16(dz[1][2 * t],     al1, bh[0], bh[1]);
                mma_f16(dz[1][2 * t + 1], al1, bh[2], bh[3]);
            }
        }

        __syncthreads();   // C: all warps past GEMM2 -> W2 buffer free

        // issue W2(ch+1): in flight across chunk boundary; wait only W1(ch+1)
        if (ch + 1 < NCHUNK) {
            cp_tileW2(sb + W2_S, g_w2s + jc + CW);
            CP_COMMIT();
            CP_WAIT1();        // W1(ch+1) done; W2(ch+1) still in flight
            __syncthreads();   // D: W1(ch+1) visible
        }
    }

    // ---------------- writeout (undo weight scale) ----------------
    #pragma unroll
    for (int mf = 0; mf < 2; mf++) {
        const int rl = mg * 32 + mf * 16 + (lane >> 2);
        #pragma unroll
        for (int nf = 0; nf < 8; nf++) {
            const int col = ng * 64 + nf * 8 + 2 * (lane & 3);
            float2 v0 = make_float2(dz[mf][nf][0] * WINV, dz[mf][nf][1] * WINV);
            float2 v1 = make_float2(dz[mf][nf][2] * WINV, dz[mf][nf][3] * WINV);
            *reinterpret_cast<float2*>(dz_out + (size_t)(row0 + rl) * D_DIM + col) = v0;
            *reinterpret_cast<float2*>(dz_out + (size_t)(row0 + rl + 8) * D_DIM + col) = v1;
        }
    }
    #pragma unroll
    for (int i = 0; i < 4; i++) {
        const int rl = mg * 32 + (i >> 1) * 16 + (lane >> 2) + 8 * (i & 1);
        atomicAdd(&sTr[rl], tr4[i]);
    }
    __syncthreads();
    if (tid < MTILE) dlog_out[row0 + tid] = -sTr[tid];
}

// ---------------------------------------------------------------------------
extern "C" void kernel_launch(void* const* d_in, const int* in_sizes, int n_in,
                              void* d_out, int out_size) {
    const float* z  = (const float*)d_in[1];
    const float* W1 = (const float*)d_in[2];
    const float* b1 = (const float*)d_in[3];
    const float* W2 = (const float*)d_in[4];

    float* dz   = (float*)d_out;
    float* dlog = dz + (size_t)BATCH * D_DIM;

    __half *zhi, *zlo, *w1s, *w2s;
    cudaGetSymbolAddress((void**)&zhi, g_z_hi);
    cudaGetSymbolAddress((void**)&zlo, g_z_lo);
    cudaGetSymbolAddress((void**)&w1s, g_w1s);
    cudaGetSymbolAddress((void**)&w2s, g_w2s);

    split_z_kernel<<<(int)((size_t)BATCH * D_DIM / 8 / 256), 256>>>(z, zhi, zlo);
    conv_w_kernel<<<(W_DIM * D_DIM / 8) / 256, 256>>>(W1, w1s);
    conv_w_kernel<<<(D_DIM * W_DIM / 8) / 256, 256>>>(W2, w2s);
    compute_M_kernel<<<W_DIM, 256>>>(W1, W2);

    cudaFuncSetAttribute(planar_mma_kernel,
                         cudaFuncAttributeMaxDynamicSharedMemorySize, S_TOTAL);
    planar_mma_kernel<<<BATCH / MTILE, 256, S_TOTAL>>>(b1, dz, dlog);
}

// round 8
// speedup vs baseline: 2.2619x; 1.3657x over previous
#include <cuda_runtime.h>
#include <cuda_fp16.h>
#include <stdint.h>
#include <math.h>

#define BATCH  65536
#define D_DIM  256
#define W_DIM  1024
#define MTILE  64
#define CW     64
#define NCHUNK (W_DIM / CW)    // 16
#define WSCALE 64.0f
#define WINV   (1.0f / 64.0f)

// device scratch: z fp16; weights scaled fp16
__device__ __align__(16) __half g_zh[(size_t)BATCH * D_DIM];
__device__ __align__(16) __half g_w1s[W_DIM * D_DIM];   // W1 * 64
__device__ __align__(16) __half g_w2s[D_DIM * W_DIM];   // W2 * 64
__device__ float g_M[W_DIM];

// ---------------- SMEM layout (bytes) ----------------
// z  : [64][264] fp16, stride 528B
// W1 : [64][264] fp16 (chunk, rows = W-col j, cols = k)
// W2 : [256][72] fp16, stride 144B
// h  : [64][72]  fp16
#define Z_S    0
#define W1_S   33792
#define W2_S   67584
#define H_S    104448
#define TR_OFF 113664
#define S_TOTAL 113920

#define ZS  528
#define W2S 144
#define HS  144

// ---------------- PTX helpers ----------------
__device__ __forceinline__ uint32_t smem_u32(const void* p) {
    uint32_t a;
    asm("{ .reg .u64 t; cvta.to.shared.u64 t, %1; cvt.u32.u64 %0, t; }" : "=r"(a) : "l"(p));
    return a;
}
#define CP_ASYNC16(d, s) \
    asm volatile("cp.async.cg.shared.global [%0], [%1], 16;" :: "r"(d), "l"(s))
#define CP_COMMIT() asm volatile("cp.async.commit_group;")
#define CP_WAIT0()  asm volatile("cp.async.wait_group 0;")
#define CP_WAIT1()  asm volatile("cp.async.wait_group 1;")

#define LDSM4(r, addr) \
    asm volatile("ldmatrix.sync.aligned.m8n8.x4.shared.b16 {%0,%1,%2,%3}, [%4];" \
        : "=r"((r)[0]), "=r"((r)[1]), "=r"((r)[2]), "=r"((r)[3]) : "r"(addr))

__device__ __forceinline__ void mma_f16(float* c, const uint32_t* a, uint32_t b0, uint32_t b1) {
    asm volatile(
        "mma.sync.aligned.m16n8k16.row.col.f32.f16.f16.f32 "
        "{%0,%1,%2,%3}, {%4,%5,%6,%7}, {%8,%9}, {%0,%1,%2,%3};"
        : "+f"(c[0]), "+f"(c[1]), "+f"(c[2]), "+f"(c[3])
        : "r"(a[0]), "r"(a[1]), "r"(a[2]), "r"(a[3]), "r"(b0), "r"(b1));
}

// ---------------- pre-pass kernels ----------------
union PackH8 { uint4 u; __half h[8]; };

__global__ void conv_kernel(const float* __restrict__ src,
                            __half* __restrict__ dst, float scale) {
    size_t gid = (size_t)blockIdx.x * 256 + threadIdx.x;
    const float4* s = reinterpret_cast<const float4*>(src);
    float4 a = s[gid * 2], b = s[gid * 2 + 1];
    float v[8] = {a.x, a.y, a.z, a.w, b.x, b.y, b.z, b.w};
    PackH8 o;
    #pragma unroll
    for (int i = 0; i < 8; i++) o.h[i] = __float2half_rn(v[i] * scale);
    reinterpret_cast<uint4*>(dst)[gid] = o.u;
}

__global__ void compute_M_kernel(const float* __restrict__ W1, const float* __restrict__ W2) {
    int j = blockIdx.x, i = threadIdx.x;
    float v = W1[j * D_DIM + i] * W2[(size_t)i * W_DIM + j];
    #pragma unroll
    for (int o = 16; o > 0; o >>= 1) v += __shfl_down_sync(0xffffffffu, v, o);
    __shared__ float red[8];
    if ((i & 31) == 0) red[i >> 5] = v;
    __syncthreads();
    if (i < 8) {
        float s = red[i];
        #pragma unroll
        for (int o = 4; o > 0; o >>= 1) s += __shfl_down_sync(0xffu, s, o);
        if (i == 0) g_M[j] = s;
    }
}

// ---------------- copy helpers (cp.async) ----------------
__device__ __forceinline__ void cp_tile256(uint32_t sdst, const __half* g, int rows) {
    int total = rows * 32;
    for (int i = threadIdx.x; i < total; i += 256) {
        int r = i >> 5, c = i & 31;
        CP_ASYNC16(sdst + r * ZS + c * 16, g + r * 256 + c * 8);
    }
}
__device__ __forceinline__ void cp_tileW2(uint32_t sdst, const __half* g) {
    for (int i = threadIdx.x; i < 256 * 8; i += 256) {
        int r = i >> 3, c = i & 7;
        CP_ASYNC16(sdst + r * W2S + c * 16, g + (size_t)r * W_DIM + c * 8);
    }
}

// ---------------- main fused kernel ----------------
__global__ void __launch_bounds__(256, 1)
planar_mma_kernel(const float* __restrict__ b1,
                  float* __restrict__ dz_out,
                  float* __restrict__ dlog_out) {
    extern __shared__ char smem[];
    const uint32_t sb = smem_u32(smem);
    float* sTr = reinterpret_cast<float*>(smem + TR_OFF);

    const int tid  = threadIdx.x;
    const int wid  = tid >> 5;
    const int lane = tid & 31;
    const int mg   = wid >> 2;     // 0/1 : rows 32*mg .. +31
    const int ng   = wid & 3;      // GEMM1: 16 cols; GEMM2: 64 cols
    const int row0 = blockIdx.x * MTILE;

    if (tid < MTILE) sTr[tid] = 0.0f;

    // prologue: z + chunk-0 weights
    cp_tile256(sb + Z_S, g_zh + (size_t)row0 * D_DIM, 64);
    cp_tile256(sb + W1_S, g_w1s, 64);
    cp_tileW2(sb + W2_S, g_w2s);
    CP_COMMIT();
    CP_WAIT0();
    __syncthreads();

    // per-lane ldmatrix base addresses
    const int lrow16 = lane & 15;
    const int lkhalf = (lane >> 4) << 3;
    const int brow   = (lane & 7) + ((lane >> 4) << 3);
    const int bkhalf = ((lane >> 3) & 1) << 3;

    const uint32_t aZ0 = sb + Z_S + (mg * 32 + lrow16) * ZS + lkhalf * 2;
    const uint32_t aZ1 = aZ0 + 16 * ZS;
    const uint32_t bW1 = sb + W1_S + (ng * 16 + brow) * ZS + bkhalf * 2;
    const uint32_t aH0 = sb + H_S + (mg * 32 + lrow16) * HS + lkhalf * 2;
    const uint32_t aH1 = aH0 + 16 * HS;
    uint32_t bW2[4];
    #pragma unroll
    for (int t = 0; t < 4; t++)
        bW2[t] = sb + W2_S + (ng * 64 + t * 16 + brow) * W2S + bkhalf * 2;

    float dz[2][8][4];
    #pragma unroll
    for (int a = 0; a < 2; a++)
        #pragma unroll
        for (int b = 0; b < 8; b++)
            #pragma unroll
            for (int c = 0; c < 4; c++) dz[a][b][c] = 0.0f;
    float tr4[4] = {0.f, 0.f, 0.f, 0.f};

    for (int ch = 0; ch < NCHUNK; ch++) {
        const int jc = ch * CW;

        // ---------- GEMM1: pre64 = z @ (64*W1chunk)^T (single fp16 term) ------
        float pre[2][2][4];
        #pragma unroll
        for (int a = 0; a < 2; a++)
            #pragma unroll
            for (int b = 0; b < 2; b++)
                #pragma unroll
                for (int c = 0; c < 4; c++) pre[a][b][c] = 0.0f;

        #pragma unroll 8
        for (int ks = 0; ks < 16; ks++) {
            const int kb = ks * 32;
            uint32_t ah0[4], ah1[4], bh[4];
            LDSM4(ah0, aZ0 + kb);
            LDSM4(ah1, aZ1 + kb);
            LDSM4(bh,  bW1 + kb);
            mma_f16(pre[0][0], ah0, bh[0], bh[1]);
            mma_f16(pre[0][1], ah0, bh[2], bh[3]);
            mma_f16(pre[1][0], ah1, bh[0], bh[1]);
            mma_f16(pre[1][1], ah1, bh[2], bh[3]);
        }

        // ---------- epilogue: x = pre/64 + b1; softplus -> h; trace -----------
        #pragma unroll
        for (int mf = 0; mf < 2; mf++) {
            #pragma unroll
            for (int nf = 0; nf < 2; nf++) {
                const int j0 = jc + ng * 16 + nf * 8 + 2 * (lane & 3);
                const float b10 = __ldg(&b1[j0]),   b11 = __ldg(&b1[j0 + 1]);
                const float M0  = g_M[j0],          M1  = g_M[j0 + 1];
                #pragma unroll
                for (int bq = 0; bq < 2; bq++) {
                    float x0 = fmaf(pre[mf][nf][2 * bq],     WINV, b10);
                    float x1 = fmaf(pre[mf][nf][2 * bq + 1], WINV, b11);
                    float e0 = __expf(-fabsf(x0)), e1 = __expf(-fabsf(x1));
                    float sp0 = fmaxf(x0, 0.0f) + __logf(1.0f + e0);
                    float sp1 = fmaxf(x1, 0.0f) + __logf(1.0f + e1);
                    float i0 = __fdividef(1.0f, 1.0f + e0);
                    float i1 = __fdividef(1.0f, 1.0f + e1);
                    float sg0 = (x0 >= 0.0f) ? i0 : e0 * i0;
                    float sg1 = (x1 >= 0.0f) ? i1 : e1 * i1;
                    tr4[mf * 2 + bq] = fmaf(sg0, M0, tr4[mf * 2 + bq]);
                    tr4[mf * 2 + bq] = fmaf(sg1, M1, tr4[mf * 2 + bq]);
                    __half h0 = __float2half_rn(sp0);
                    __half h1 = __float2half_rn(sp1);
                    uint32_t phi = ((uint32_t)__half_as_ushort(h1) << 16) |
                                   (uint32_t)__half_as_ushort(h0);
                    const int rl = mg * 32 + mf * 16 + (lane >> 2) + 8 * bq;
                    const int cl = ng * 16 + nf * 8 + 2 * (lane & 3);
                    const uint32_t ha = sb + H_S + rl * HS + cl * 2;
                    asm volatile("st.shared.b32 [%0], %1;" :: "r"(ha), "r"(phi) : "memory");
                }
            }
        }

        __syncthreads();   // A: all warps past GEMM1 -> W1 buffer free

        // issue W1(ch+1): hidden under GEMM2(ch)
        if (ch + 1 < NCHUNK) {
            cp_tile256(sb + W1_S, g_w1s + (size_t)(jc + CW) * D_DIM, 64);
            CP_COMMIT();
        }
        // wait for W2(ch) (issued at tail of ch-1), leave W1(ch+1) in flight
        if (ch > 0) {
            if (ch + 1 < NCHUNK) CP_WAIT1(); else CP_WAIT0();
        }
        __syncthreads();   // B: h + W2(ch) visible

        // ---------- GEMM2: dz64 += h @ (64*W2chunk) (single fp16 term) --------
        #pragma unroll
        for (int ks = 0; ks < 4; ks++) {
            const int kb = ks * 32;
            uint32_t ah0[4], ah1[4];
            LDSM4(ah0, aH0 + kb);
            LDSM4(ah1, aH1 + kb);
            #pragma unroll
            for (int t = 0; t < 4; t++) {
                uint32_t bh[4];
                LDSM4(bh, bW2[t] + kb);
                mma_f16(dz[0][2 * t],     ah0, bh[0], bh[1]);
                mma_f16(dz[0][2 * t + 1], ah0, bh[2], bh[3]);
                mma_f16(dz[1][2 * t],     ah1, bh[0], bh[1]);
                mma_f16(dz[1][2 * t + 1], ah1, bh[2], bh[3]);
            }
        }

        __syncthreads();   // C: all warps past GEMM2 -> W2 buffer free

        // issue W2(ch+1): in flight across chunk boundary; wait only W1(ch+1)
        if (ch + 1 < NCHUNK) {
            cp_tileW2(sb + W2_S, g_w2s + jc + CW);
            CP_COMMIT();
            CP_WAIT1();        // W1(ch+1) done; W2(ch+1) still in flight
            __syncthreads();   // D: W1(ch+1) visible
        }
    }

    // ---------------- writeout (undo weight scale) ----------------
    #pragma unroll
    for (int mf = 0; mf < 2; mf++) {
        const int rl = mg * 32 + mf * 16 + (lane >> 2);
        #pragma unroll
        for (int nf = 0; nf < 8; nf++) {
            const int col = ng * 64 + nf * 8 + 2 * (lane & 3);
            float2 v0 = make_float2(dz[mf][nf][0] * WINV, dz[mf][nf][1] * WINV);
            float2 v1 = make_float2(dz[mf][nf][2] * WINV, dz[mf][nf][3] * WINV);
            *reinterpret_cast<float2*>(dz_out + (size_t)(row0 + rl) * D_DIM + col) = v0;
            *reinterpret_cast<float2*>(dz_out + (size_t)(row0 + rl + 8) * D_DIM + col) = v1;
        }
    }
    #pragma unroll
    for (int i = 0; i < 4; i++) {
        const int rl = mg * 32 + (i >> 1) * 16 + (lane >> 2) + 8 * (i & 1);
        atomicAdd(&sTr[rl], tr4[i]);
    }
    __syncthreads();
    if (tid < MTILE) dlog_out[row0 + tid] = -sTr[tid];
}

// ---------------------------------------------------------------------------
extern "C" void kernel_launch(void* const* d_in, const int* in_sizes, int n_in,
                              void* d_out, int out_size) {
    const float* z  = (const float*)d_in[1];
    const float* W1 = (const float*)d_in[2];
    const float* b1 = (const float*)d_in[3];
    const float* W2 = (const float*)d_in[4];

    float* dz   = (float*)d_out;
    float* dlog = dz + (size_t)BATCH * D_DIM;

    __half *zh, *w1s, *w2s;
    cudaGetSymbolAddress((void**)&zh,  g_zh);
    cudaGetSymbolAddress((void**)&w1s, g_w1s);
    cudaGetSymbolAddress((void**)&w2s, g_w2s);

    conv_kernel<<<(int)((size_t)BATCH * D_DIM / 8 / 256), 256>>>(z, zh, 1.0f);
    conv_kernel<<<(W_DIM * D_DIM / 8) / 256, 256>>>(W1, w1s, WSCALE);
    conv_kernel<<<(D_DIM * W_DIM / 8) / 256, 256>>>(W2, w2s, WSCALE);
    compute_M_kernel<<<W_DIM, 256>>>(W1, W2);

    cudaFuncSetAttribute(planar_mma_kernel,
                         cudaFuncAttributeMaxDynamicSharedMemorySize, S_TOTAL);
    planar_mma_kernel<<<BATCH / MTILE, 256, S_TOTAL>>>(b1, dz, dlog);
}

// round 9
// speedup vs baseline: 2.4680x; 1.0911x over previous
#include <cuda_runtime.h>
#include <cuda_fp16.h>
#include <stdint.h>
#include <math.h>

#define BATCH  65536
#define D_DIM  256
#define W_DIM  1024
#define MTILE  128
#define NTHREADS 512
#define CW     64
#define NCHUNK (W_DIM / CW)    // 16
#define WSCALE 64.0f
#define WINV   (1.0f / 64.0f)

// device scratch: z fp16; weights scaled fp16
__device__ __align__(16) __half g_zh[(size_t)BATCH * D_DIM];
__device__ __align__(16) __half g_w1s[W_DIM * D_DIM];   // W1 * 64
__device__ __align__(16) __half g_w2s[D_DIM * W_DIM];   // W2 * 64
__device__ float g_M[W_DIM];

// ---------------- SMEM layout (bytes) ----------------
// z  : [128][264] fp16, stride 528B
// W1 : [64][264] fp16 (chunk, rows = W-col j, cols = k)
// W2 : [256][72] fp16, stride 144B
// h  : [128][72] fp16
#define Z_S    0
#define W1_S   67584
#define W2_S   101376
#define H_S    138240
#define TR_OFF 156672
#define S_TOTAL 157184

#define ZS  528
#define W2S 144
#define HS  144

// ---------------- PTX helpers ----------------
__device__ __forceinline__ uint32_t smem_u32(const void* p) {
    uint32_t a;
    asm("{ .reg .u64 t; cvta.to.shared.u64 t, %1; cvt.u32.u64 %0, t; }" : "=r"(a) : "l"(p));
    return a;
}
#define CP_ASYNC16(d, s) \
    asm volatile("cp.async.cg.shared.global [%0], [%1], 16;" :: "r"(d), "l"(s))
#define CP_COMMIT() asm volatile("cp.async.commit_group;")
#define CP_WAIT0()  asm volatile("cp.async.wait_group 0;")
#define CP_WAIT1()  asm volatile("cp.async.wait_group 1;")

#define LDSM4(r, addr) \
    asm volatile("ldmatrix.sync.aligned.m8n8.x4.shared.b16 {%0,%1,%2,%3}, [%4];" \
        : "=r"((r)[0]), "=r"((r)[1]), "=r"((r)[2]), "=r"((r)[3]) : "r"(addr))

__device__ __forceinline__ void mma_f16(float* c, const uint32_t* a, uint32_t b0, uint32_t b1) {
    asm volatile(
        "mma.sync.aligned.m16n8k16.row.col.f32.f16.f16.f32 "
        "{%0,%1,%2,%3}, {%4,%5,%6,%7}, {%8,%9}, {%0,%1,%2,%3};"
        : "+f"(c[0]), "+f"(c[1]), "+f"(c[2]), "+f"(c[3])
        : "r"(a[0]), "r"(a[1]), "r"(a[2]), "r"(a[3]), "r"(b0), "r"(b1));
}

// ---------------- pre-pass kernels ----------------
union PackH8 { uint4 u; __half h[8]; };

__global__ void conv_kernel(const float* __restrict__ src,
                            __half* __restrict__ dst, float scale) {
    size_t gid = (size_t)blockIdx.x * 256 + threadIdx.x;
    const float4* s = reinterpret_cast<const float4*>(src);
    float4 a = s[gid * 2], b = s[gid * 2 + 1];
    float v[8] = {a.x, a.y, a.z, a.w, b.x, b.y, b.z, b.w};
    PackH8 o;
    #pragma unroll
    for (int i = 0; i < 8; i++) o.h[i] = __float2half_rn(v[i] * scale);
    reinterpret_cast<uint4*>(dst)[gid] = o.u;
}

__global__ void compute_M_kernel(const float* __restrict__ W1, const float* __restrict__ W2) {
    int j = blockIdx.x, i = threadIdx.x;
    float v = W1[j * D_DIM + i] * W2[(size_t)i * W_DIM + j];
    #pragma unroll
    for (int o = 16; o > 0; o >>= 1) v += __shfl_down_sync(0xffffffffu, v, o);
    __shared__ float red[8];
    if ((i & 31) == 0) red[i >> 5] = v;
    __syncthreads();
    if (i < 8) {
        float s = red[i];
        #pragma unroll
        for (int o = 4; o > 0; o >>= 1) s += __shfl_down_sync(0xffu, s, o);
        if (i == 0) g_M[j] = s;
    }
}

// ---------------- copy helpers (cp.async, 512 threads) ----------------
__device__ __forceinline__ void cp_tile256(uint32_t sdst, const __half* g, int rows) {
    int total = rows * 32;
    for (int i = threadIdx.x; i < total; i += NTHREADS) {
        int r = i >> 5, c = i & 31;
        CP_ASYNC16(sdst + r * ZS + c * 16, g + r * 256 + c * 8);
    }
}
__device__ __forceinline__ void cp_tileW2(uint32_t sdst, const __half* g) {
    for (int i = threadIdx.x; i < 256 * 8; i += NTHREADS) {
        int r = i >> 3, c = i & 7;
        CP_ASYNC16(sdst + r * W2S + c * 16, g + (size_t)r * W_DIM + c * 8);
    }
}

// ---------------- main fused kernel ----------------
__global__ void __launch_bounds__(NTHREADS, 1)
planar_mma_kernel(const float* __restrict__ b1,
                  float* __restrict__ dz_out,
                  float* __restrict__ dlog_out) {
    extern __shared__ char smem[];
    const uint32_t sb = smem_u32(smem);
    float* sTr = reinterpret_cast<float*>(smem + TR_OFF);

    const int tid  = threadIdx.x;
    const int wid  = tid >> 5;
    const int lane = tid & 31;
    const int mg   = wid >> 2;     // 0..3 : rows 32*mg .. +31
    const int ng   = wid & 3;      // GEMM1: 16 cols; GEMM2: 64 cols
    const int row0 = blockIdx.x * MTILE;

    if (tid < MTILE) sTr[tid] = 0.0f;

    // prologue: z + chunk-0 weights
    cp_tile256(sb + Z_S, g_zh + (size_t)row0 * D_DIM, MTILE);
    cp_tile256(sb + W1_S, g_w1s, 64);
    cp_tileW2(sb + W2_S, g_w2s);
    CP_COMMIT();
    CP_WAIT0();
    __syncthreads();

    // per-lane ldmatrix base addresses
    const int lrow16 = lane & 15;
    const int lkhalf = (lane >> 4) << 3;
    const int brow   = (lane & 7) + ((lane >> 4) << 3);
    const int bkhalf = ((lane >> 3) & 1) << 3;

    const uint32_t aZ0 = sb + Z_S + (mg * 32 + lrow16) * ZS + lkhalf * 2;
    const uint32_t aZ1 = aZ0 + 16 * ZS;
    const uint32_t bW1 = sb + W1_S + (ng * 16 + brow) * ZS + bkhalf * 2;
    const uint32_t aH0 = sb + H_S + (mg * 32 + lrow16) * HS + lkhalf * 2;
    const uint32_t aH1 = aH0 + 16 * HS;
    uint32_t bW2[4];
    #pragma unroll
    for (int t = 0; t < 4; t++)
        bW2[t] = sb + W2_S + (ng * 64 + t * 16 + brow) * W2S + bkhalf * 2;

    float dz[2][8][4];
    #pragma unroll
    for (int a = 0; a < 2; a++)
        #pragma unroll
        for (int b = 0; b < 8; b++)
            #pragma unroll
            for (int c = 0; c < 4; c++) dz[a][b][c] = 0.0f;
    float tr4[4] = {0.f, 0.f, 0.f, 0.f};

    for (int ch = 0; ch < NCHUNK; ch++) {
        const int jc = ch * CW;

        // ---------- GEMM1: pre = z @ (64*W1chunk)^T (single fp16 term) --------
        float pre[2][2][4];
        #pragma unroll
        for (int a = 0; a < 2; a++)
            #pragma unroll
            for (int b = 0; b < 2; b++)
                #pragma unroll
                for (int c = 0; c < 4; c++) pre[a][b][c] = 0.0f;

        #pragma unroll 8
        for (int ks = 0; ks < 16; ks++) {
            const int kb = ks * 32;
            uint32_t ah0[4], ah1[4], bh[4];
            LDSM4(ah0, aZ0 + kb);
            LDSM4(ah1, aZ1 + kb);
            LDSM4(bh,  bW1 + kb);
            mma_f16(pre[0][0], ah0, bh[0], bh[1]);
            mma_f16(pre[0][1], ah0, bh[2], bh[3]);
            mma_f16(pre[1][0], ah1, bh[0], bh[1]);
            mma_f16(pre[1][1], ah1, bh[2], bh[3]);
        }

        // ---------- epilogue: x = pre/64 + b1; softplus -> h; trace -----------
        #pragma unroll
        for (int mf = 0; mf < 2; mf++) {
            #pragma unroll
            for (int nf = 0; nf < 2; nf++) {
                const int j0 = jc + ng * 16 + nf * 8 + 2 * (lane & 3);
                const float b10 = __ldg(&b1[j0]),   b11 = __ldg(&b1[j0 + 1]);
                const float M0  = g_M[j0],          M1  = g_M[j0 + 1];
                #pragma unroll
                for (int bq = 0; bq < 2; bq++) {
                    float x0 = fmaf(pre[mf][nf][2 * bq],     WINV, b10);
                    float x1 = fmaf(pre[mf][nf][2 * bq + 1], WINV, b11);
                    float e0 = __expf(-fabsf(x0)), e1 = __expf(-fabsf(x1));
                    float sp0 = fmaxf(x0, 0.0f) + __logf(1.0f + e0);
                    float sp1 = fmaxf(x1, 0.0f) + __logf(1.0f + e1);
                    float i0 = __fdividef(1.0f, 1.0f + e0);
                    float i1 = __fdividef(1.0f, 1.0f + e1);
                    float sg0 = (x0 >= 0.0f) ? i0 : e0 * i0;
                    float sg1 = (x1 >= 0.0f) ? i1 : e1 * i1;
                    tr4[mf * 2 + bq] = fmaf(sg0, M0, tr4[mf * 2 + bq]);
                    tr4[mf * 2 + bq] = fmaf(sg1, M1, tr4[mf * 2 + bq]);
                    __half h0 = __float2half_rn(sp0);
                    __half h1 = __float2half_rn(sp1);
                    uint32_t phi = ((uint32_t)__half_as_ushort(h1) << 16) |
                                   (uint32_t)__half_as_ushort(h0);
                    const int rl = mg * 32 + mf * 16 + (lane >> 2) + 8 * bq;
                    const int cl = ng * 16 + nf * 8 + 2 * (lane & 3);
                    const uint32_t ha = sb + H_S + rl * HS + cl * 2;
                    asm volatile("st.shared.b32 [%0], %1;" :: "r"(ha), "r"(phi) : "memory");
                }
            }
        }

        __syncthreads();   // A: all warps past GEMM1 -> W1 buffer free

        // issue W1(ch+1): hidden under GEMM2(ch)
        if (ch + 1 < NCHUNK) {
            cp_tile256(sb + W1_S, g_w1s + (size_t)(jc + CW) * D_DIM, 64);
            CP_COMMIT();
        }
        // wait for W2(ch) (issued at tail of ch-1), leave W1(ch+1) in flight
        if (ch > 0) {
            if (ch + 1 < NCHUNK) CP_WAIT1(); else CP_WAIT0();
        }
        __syncthreads();   // B: h + W2(ch) visible

        // ---------- GEMM2: dz += h @ (64*W2chunk) (single fp16 term) ----------
        #pragma unroll
        for (int ks = 0; ks < 4; ks++) {
            const int kb = ks * 32;
            uint32_t ah0[4], ah1[4];
            LDSM4(ah0, aH0 + kb);
            LDSM4(ah1, aH1 + kb);
            #pragma unroll
            for (int t = 0; t < 4; t++) {
                uint32_t bh[4];
                LDSM4(bh, bW2[t] + kb);
                mma_f16(dz[0][2 * t],     ah0, bh[0], bh[1]);
                mma_f16(dz[0][2 * t + 1], ah0, bh[2], bh[3]);
                mma_f16(dz[1][2 * t],     ah1, bh[0], bh[1]);
                mma_f16(dz[1][2 * t + 1], ah1, bh[2], bh[3]);
            }
        }

        __syncthreads();   // C: all warps past GEMM2 -> W2 buffer free

        // issue W2(ch+1): in flight across chunk boundary; wait only W1(ch+1)
        if (ch + 1 < NCHUNK) {
            cp_tileW2(sb + W2_S, g_w2s + jc + CW);
            CP_COMMIT();
            CP_WAIT1();        // W1(ch+1) done; W2(ch+1) still in flight
            __syncthreads();   // D: W1(ch+1) visible
        }
    }

    // ---------------- writeout (undo weight scale) ----------------
    #pragma unroll
    for (int mf = 0; mf < 2; mf++) {
        const int rl = mg * 32 + mf * 16 + (lane >> 2);
        #pragma unroll
        for (int nf = 0; nf < 8; nf++) {
            const int col = ng * 64 + nf * 8 + 2 * (lane & 3);
            float2 v0 = make_float2(dz[mf][nf][0] * WINV, dz[mf][nf][1] * WINV);
            float2 v1 = make_float2(dz[mf][nf][2] * WINV, dz[mf][nf][3] * WINV);
            *reinterpret_cast<float2*>(dz_out + (size_t)(row0 + rl) * D_DIM + col) = v0;
            *reinterpret_cast<float2*>(dz_out + (size_t)(row0 + rl + 8) * D_DIM + col) = v1;
        }
    }
    #pragma unroll
    for (int i = 0; i < 4; i++) {
        const int rl = mg * 32 + (i >> 1) * 16 + (lane >> 2) + 8 * (i & 1);
        atomicAdd(&sTr[rl], tr4[i]);
    }
    __syncthreads();
    if (tid < MTILE) dlog_out[row0 + tid] = -sTr[tid];
}

// ---------------------------------------------------------------------------
extern "C" void kernel_launch(void* const* d_in, const int* in_sizes, int n_in,
                              void* d_out, int out_size) {
    const float* z  = (const float*)d_in[1];
    const float* W1 = (const float*)d_in[2];
    const float* b1 = (const float*)d_in[3];
    const float* W2 = (const float*)d_in[4];

    float* dz   = (float*)d_out;
    float* dlog = dz + (size_t)BATCH * D_DIM;

    __half *zh, *w1s, *w2s;
    cudaGetSymbolAddress((void**)&zh,  g_zh);
    cudaGetSymbolAddress((void**)&w1s, g_w1s);
    cudaGetSymbolAddress((void**)&w2s, g_w2s);

    conv_kernel<<<(int)((size_t)BATCH * D_DIM / 8 / 256), 256>>>(z, zh, 1.0f);
    conv_kernel<<<(W_DIM * D_DIM / 8) / 256, 256>>>(W1, w1s, WSCALE);
    conv_kernel<<<(D_DIM * W_DIM / 8) / 256, 256>>>(W2, w2s, WSCALE);
    compute_M_kernel<<<W_DIM, 256>>>(W1, W2);

    cudaFuncSetAttribute(planar_mma_kernel,
                         cudaFuncAttributeMaxDynamicSharedMemorySize, S_TOTAL);
    planar_mma_kernel<<<BATCH / MTILE, NTHREADS, S_TOTAL>>>(b1, dz, dlog);
}

// round 10
// speedup vs baseline: 2.8367x; 1.1494x over previous
#include <cuda_runtime.h>
#include <cuda_fp16.h>
#include <stdint.h>
#include <math.h>

#define BATCH  65536
#define D_DIM  256
#define W_DIM  1024
#define MTILE  128
#define NTHREADS 512
#define CW     128
#define NCHUNK (W_DIM / CW)    // 8
#define WSCALE 64.0f
#define WINV   (1.0f / 64.0f)

// device scratch: z fp16; weights scaled fp16
__device__ __align__(16) __half g_zh[(size_t)BATCH * D_DIM];
__device__ __align__(16) __half g_w1s[W_DIM * D_DIM];   // W1 * 64
__device__ __align__(16) __half g_w2s[D_DIM * W_DIM];   // W2 * 64
__device__ float g_M[W_DIM];

// ---------------- SMEM layout (bytes), XOR-swizzled, pad-free ----------------
// z  : [128][512B]  (256 fp16/row)   addr = r*512 + ((ku ^ (r&7))<<4)
// W1 : [128][512B]  chunk rows = W-col j
// W2 : [256][256B]  chunk (128 fp16/row)
// h  : [128][256B]
#define Z_S    0
#define W1_S   65536
#define W2_S   131072
#define H_S    196608
#define TR_OFF 229376
#define S_TOTAL 229888

// ---------------- PTX helpers ----------------
__device__ __forceinline__ uint32_t smem_u32(const void* p) {
    uint32_t a;
    asm("{ .reg .u64 t; cvta.to.shared.u64 t, %1; cvt.u32.u64 %0, t; }" : "=r"(a) : "l"(p));
    return a;
}
#define CP_ASYNC16(d, s) \
    asm volatile("cp.async.cg.shared.global [%0], [%1], 16;" :: "r"(d), "l"(s))
#define CP_COMMIT() asm volatile("cp.async.commit_group;")
#define CP_WAIT0()  asm volatile("cp.async.wait_group 0;")
#define CP_WAIT1()  asm volatile("cp.async.wait_group 1;")

#define LDSM4(r, addr) \
    asm volatile("ldmatrix.sync.aligned.m8n8.x4.shared.b16 {%0,%1,%2,%3}, [%4];" \
        : "=r"((r)[0]), "=r"((r)[1]), "=r"((r)[2]), "=r"((r)[3]) : "r"(addr))

__device__ __forceinline__ void mma_f16(float* c, const uint32_t* a, uint32_t b0, uint32_t b1) {
    asm volatile(
        "mma.sync.aligned.m16n8k16.row.col.f32.f16.f16.f32 "
        "{%0,%1,%2,%3}, {%4,%5,%6,%7}, {%8,%9}, {%0,%1,%2,%3};"
        : "+f"(c[0]), "+f"(c[1]), "+f"(c[2]), "+f"(c[3])
        : "r"(a[0]), "r"(a[1]), "r"(a[2]), "r"(a[3]), "r"(b0), "r"(b1));
}

// ---------------- pre-pass kernels ----------------
union PackH8 { uint4 u; __half h[8]; };

__global__ void conv_kernel(const float* __restrict__ src,
                            __half* __restrict__ dst, float scale) {
    size_t gid = (size_t)blockIdx.x * 256 + threadIdx.x;
    const float4* s = reinterpret_cast<const float4*>(src);
    float4 a = s[gid * 2], b = s[gid * 2 + 1];
    float v[8] = {a.x, a.y, a.z, a.w, b.x, b.y, b.z, b.w};
    PackH8 o;
    #pragma unroll
    for (int i = 0; i < 8; i++) o.h[i] = __float2half_rn(v[i] * scale);
    reinterpret_cast<uint4*>(dst)[gid] = o.u;
}

__global__ void compute_M_kernel(const float* __restrict__ W1, const float* __restrict__ W2) {
    int j = blockIdx.x, i = threadIdx.x;
    float v = W1[j * D_DIM + i] * W2[(size_t)i * W_DIM + j];
    #pragma unroll
    for (int o = 16; o > 0; o >>= 1) v += __shfl_down_sync(0xffffffffu, v, o);
    __shared__ float red[8];
    if ((i & 31) == 0) red[i >> 5] = v;
    __syncthreads();
    if (i < 8) {
        float s = red[i];
        #pragma unroll
        for (int o = 4; o > 0; o >>= 1) s += __shfl_down_sync(0xffu, s, o);
        if (i == 0) g_M[j] = s;
    }
}

// ---------------- copy helpers (cp.async, 512 threads, swizzled dst) ---------
// 128 rows x 256 fp16 (512B rows)
__device__ __forceinline__ void cp_tile512(uint32_t sdst, const __half* g) {
    for (int i = threadIdx.x; i < 4096; i += NTHREADS) {
        int r = i >> 5, cu = i & 31;
        CP_ASYNC16(sdst + r * 512 + ((cu ^ (r & 7)) << 4), g + r * 256 + cu * 8);
    }
}
// 256 rows x 128 fp16 (256B rows), src rows stride W_DIM
__device__ __forceinline__ void cp_tileW2(uint32_t sdst, const __half* g) {
    for (int i = threadIdx.x; i < 4096; i += NTHREADS) {
        int r = i >> 4, cu = i & 15;
        CP_ASYNC16(sdst + r * 256 + ((cu ^ (r & 7)) << 4), g + (size_t)r * W_DIM + cu * 8);
    }
}

// ---------------- main fused kernel ----------------
__global__ void __launch_bounds__(NTHREADS, 1)
planar_mma_kernel(const float* __restrict__ b1,
                  float* __restrict__ dz_out,
                  float* __restrict__ dlog_out) {
    extern __shared__ char smem[];
    const uint32_t sb = smem_u32(smem);
    float* sTr = reinterpret_cast<float*>(smem + TR_OFF);

    const int tid  = threadIdx.x;
    const int wid  = tid >> 5;
    const int lane = tid & 31;
    const int mg   = wid >> 2;     // 0..3 : rows 32*mg .. +31
    const int ng   = wid & 3;      // GEMM1: 32 cols; GEMM2: 64 cols
    const int row0 = blockIdx.x * MTILE;

    if (tid < MTILE) sTr[tid] = 0.0f;

    // prologue: z + chunk-0 weights
    cp_tile512(sb + Z_S, g_zh + (size_t)row0 * D_DIM);
    cp_tile512(sb + W1_S, g_w1s);
    cp_tileW2(sb + W2_S, g_w2s);
    CP_COMMIT();
    CP_WAIT0();
    __syncthreads();

    // per-lane fragment addressing (XOR swizzle; swz == lane&7 for all reads)
    const int lr    = lane & 15;
    const int kodd  = lane >> 4;          // A operands
    const int brow  = (lane & 7) + ((lane >> 4) << 3);
    const int koddb = (lane >> 3) & 1;    // B operands
    const int swz   = lane & 7;

    const uint32_t zbase  = sb + Z_S  + (mg * 32 + lr) * 512;
    const uint32_t w1base = sb + W1_S + (ng * 32 + brow) * 512;
    const uint32_t hbase  = sb + H_S  + (mg * 32 + lr) * 256;
    const uint32_t w2base = sb + W2_S + (ng * 64 + brow) * 256;

    float dz[2][8][4];
    #pragma unroll
    for (int a = 0; a < 2; a++)
        #pragma unroll
        for (int b = 0; b < 8; b++)
            #pragma unroll
            for (int c = 0; c < 4; c++) dz[a][b][c] = 0.0f;
    float tr4[4] = {0.f, 0.f, 0.f, 0.f};

    for (int ch = 0; ch < NCHUNK; ch++) {
        const int jc = ch * CW;

        // ---------- GEMM1: pre[128x128] = z @ (64*W1chunk)^T, warp m32n32 -----
        float pre[2][4][4];
        #pragma unroll
        for (int a = 0; a < 2; a++)
            #pragma unroll
            for (int b = 0; b < 4; b++)
                #pragma unroll
                for (int c = 0; c < 4; c++) pre[a][b][c] = 0.0f;

        #pragma unroll 8
        for (int ks = 0; ks < 16; ks++) {
            const uint32_t offA = (uint32_t)(((ks * 2 + kodd)  ^ swz) << 4);
            const uint32_t offB = (uint32_t)(((ks * 2 + koddb) ^ swz) << 4);
            uint32_t ah0[4], ah1[4], bh0[4], bh1[4];
            LDSM4(ah0, zbase + offA);
            LDSM4(ah1, zbase + 16 * 512 + offA);
            LDSM4(bh0, w1base + offB);
            LDSM4(bh1, w1base + 16 * 512 + offB);
            mma_f16(pre[0][0], ah0, bh0[0], bh0[1]);
            mma_f16(pre[0][1], ah0, bh0[2], bh0[3]);
            mma_f16(pre[0][2], ah0, bh1[0], bh1[1]);
            mma_f16(pre[0][3], ah0, bh1[2], bh1[3]);
            mma_f16(pre[1][0], ah1, bh0[0], bh0[1]);
            mma_f16(pre[1][1], ah1, bh0[2], bh0[3]);
            mma_f16(pre[1][2], ah1, bh1[0], bh1[1]);
            mma_f16(pre[1][3], ah1, bh1[2], bh1[3]);
        }

        // ---------- epilogue: x = pre/64 + b1; softplus -> h (swizzled); trace -
        #pragma unroll
        for (int mf = 0; mf < 2; mf++) {
            #pragma unroll
            for (int nf = 0; nf < 4; nf++) {
                const int j0 = jc + ng * 32 + nf * 8 + 2 * (lane & 3);
                const float b10 = __ldg(&b1[j0]),   b11 = __ldg(&b1[j0 + 1]);
                const float M0  = g_M[j0],          M1  = g_M[j0 + 1];
                const int clu = ng * 4 + nf;       // 16B-unit column index
                #pragma unroll
                for (int bq = 0; bq < 2; bq++) {
                    float x0 = fmaf(pre[mf][nf][2 * bq],     WINV, b10);
                    float x1 = fmaf(pre[mf][nf][2 * bq + 1], WINV, b11);
                    float e0 = __expf(-fabsf(x0)), e1 = __expf(-fabsf(x1));
                    float sp0 = fmaxf(x0, 0.0f) + __logf(1.0f + e0);
                    float sp1 = fmaxf(x1, 0.0f) + __logf(1.0f + e1);
                    float i0 = __fdividef(1.0f, 1.0f + e0);
                    float i1 = __fdividef(1.0f, 1.0f + e1);
                    float sg0 = (x0 >= 0.0f) ? i0 : e0 * i0;
                    float sg1 = (x1 >= 0.0f) ? i1 : e1 * i1;
                    tr4[mf * 2 + bq] = fmaf(sg0, M0, tr4[mf * 2 + bq]);
                    tr4[mf * 2 + bq] = fmaf(sg1, M1, tr4[mf * 2 + bq]);
                    __half h0 = __float2half_rn(sp0);
                    __half h1 = __float2half_rn(sp1);
                    uint32_t phi = ((uint32_t)__half_as_ushort(h1) << 16) |
                                   (uint32_t)__half_as_ushort(h0);
                    const int rl = mg * 32 + mf * 16 + (lane >> 2) + 8 * bq;
                    const uint32_t ha = sb + H_S + rl * 256 +
                                        (((uint32_t)(clu ^ (rl & 7))) << 4) +
                                        (lane & 3) * 4;
                    asm volatile("st.shared.b32 [%0], %1;" :: "r"(ha), "r"(phi) : "memory");
                }
            }
        }

        __syncthreads();   // A: all warps past GEMM1 -> W1 buffer free

        // issue W1(ch+1): hidden under GEMM2(ch)
        if (ch + 1 < NCHUNK) {
            cp_tile512(sb + W1_S, g_w1s + (size_t)(jc + CW) * D_DIM);
            CP_COMMIT();
        }
        // wait for W2(ch) (issued at tail of ch-1), leave W1(ch+1) in flight
        if (ch > 0) {
            if (ch + 1 < NCHUNK) CP_WAIT1(); else CP_WAIT0();
        }
        __syncthreads();   // B: h + W2(ch) visible

        // ---------- GEMM2: dz += h @ (64*W2chunk), warp m32n64, K=128 ---------
        #pragma unroll
        for (int ks = 0; ks < 8; ks++) {
            const uint32_t offA = (uint32_t)(((ks * 2 + kodd)  ^ swz) << 4);
            const uint32_t offB = (uint32_t)(((ks * 2 + koddb) ^ swz) << 4);
            uint32_t ah0[4], ah1[4];
            LDSM4(ah0, hbase + offA);
            LDSM4(ah1, hbase + 16 * 256 + offA);
            #pragma unroll
            for (int t = 0; t < 4; t++) {
                uint32_t bh[4];
                LDSM4(bh, w2base + t * 16 * 256 + offB);
                mma_f16(dz[0][2 * t],     ah0, bh[0], bh[1]);
                mma_f16(dz[0][2 * t + 1], ah0, bh[2], bh[3]);
                mma_f16(dz[1][2 * t],     ah1, bh[0], bh[1]);
                mma_f16(dz[1][2 * t + 1], ah1, bh[2], bh[3]);
            }
        }

        __syncthreads();   // C: all warps past GEMM2 -> W2 buffer free

        // issue W2(ch+1): in flight across chunk boundary; wait only W1(ch+1)
        if (ch + 1 < NCHUNK) {
            cp_tileW2(sb + W2_S, g_w2s + jc + CW);
            CP_COMMIT();
            CP_WAIT1();        // W1(ch+1) done; W2(ch+1) still in flight
            __syncthreads();   // D: W1(ch+1) visible
        }
    }

    // ---------------- writeout (undo weight scale) ----------------
    #pragma unroll
    for (int mf = 0; mf < 2; mf++) {
        const int rl = mg * 32 + mf * 16 + (lane >> 2);
        #pragma unroll
        for (int nf = 0; nf < 8; nf++) {
            const int col = ng * 64 + nf * 8 + 2 * (lane & 3);
            float2 v0 = make_float2(dz[mf][nf][0] * WINV, dz[mf][nf][1] * WINV);
            float2 v1 = make_float2(dz[mf][nf][2] * WINV, dz[mf][nf][3] * WINV);
            *reinterpret_cast<float2*>(dz_out + (size_t)(row0 + rl) * D_DIM + col) = v0;
            *reinterpret_cast<float2*>(dz_out + (size_t)(row0 + rl + 8) * D_DIM + col) = v1;
        }
    }
    #pragma unroll
    for (int i = 0; i < 4; i++) {
        const int rl = mg * 32 + (i >> 1) * 16 + (lane >> 2) + 8 * (i & 1);
        atomicAdd(&sTr[rl], tr4[i]);
    }
    __syncthreads();
    if (tid < MTILE) dlog_out[row0 + tid] = -sTr[tid];
}

// ---------------------------------------------------------------------------
extern "C" void kernel_launch(void* const* d_in, const int* in_sizes, int n_in,
                              void* d_out, int out_size) {
    const float* z  = (const float*)d_in[1];
    const float* W1 = (const float*)d_in[2];
    const float* b1 = (const float*)d_in[3];
    const float* W2 = (const float*)d_in[4];

    float* dz   = (float*)d_out;
    float* dlog = dz + (size_t)BATCH * D_DIM;

    __half *zh, *w1s, *w2s;
    cudaGetSymbolAddress((void**)&zh,  g_zh);
    cudaGetSymbolAddress((void**)&w1s, g_w1s);
    cudaGetSymbolAddress((void**)&w2s, g_w2s);

    conv_kernel<<<(int)((size_t)BATCH * D_DIM / 8 / 256), 256>>>(z, zh, 1.0f);
    conv_kernel<<<(W_DIM * D_DIM / 8) / 256, 256>>>(W1, w1s, WSCALE);
    conv_kernel<<<(D_DIM * W_DIM / 8) / 256, 256>>>(W2, w2s, WSCALE);
    compute_M_kernel<<<W_DIM, 256>>>(W1, W2);

    cudaFuncSetAttribute(planar_mma_kernel,
                         cudaFuncAttributeMaxDynamicSharedMemorySize, S_TOTAL);
    planar_mma_kernel<<<BATCH / MTILE, NTHREADS, S_TOTAL>>>(b1, dz, dlog);
}

// round 11
// speedup vs baseline: 3.0968x; 1.0917x over previous
#include <cuda_runtime.h>
#include <cuda_fp16.h>
#include <stdint.h>
#include <math.h>

#define BATCH  65536
#define D_DIM  256
#define W_DIM  1024
#define MTILE  128
#define NTHREADS 512
#define CW     128
#define NCHUNK (W_DIM / CW)    // 8
#define WSCALE 64.0f
#define WINV   (1.0f / 64.0f)

// tail-split: 444 full tiles (128 rows) + 136 half tiles (64 rows)
#define NFULL  444
#define NHALF  136
#define NGRID  (NFULL + NHALF)          // 580
#define ROWS_FULL_TOTAL (NFULL * MTILE) // 56832

// device scratch: z fp16; weights scaled fp16
__device__ __align__(16) __half g_zh[(size_t)BATCH * D_DIM];
__device__ __align__(16) __half g_w1s[W_DIM * D_DIM];   // W1 * 64
__device__ __align__(16) __half g_w2s[D_DIM * W_DIM];   // W2 * 64
__device__ float g_M[W_DIM];

// ---------------- SMEM layout (bytes), XOR-swizzled, pad-free ----------------
#define Z_S    0
#define W1_S   65536
#define W2_S   131072
#define H_S    196608
#define TR_OFF 229376
#define S_TOTAL 229888

// ---------------- PTX helpers ----------------
__device__ __forceinline__ uint32_t smem_u32(const void* p) {
    uint32_t a;
    asm("{ .reg .u64 t; cvta.to.shared.u64 t, %1; cvt.u32.u64 %0, t; }" : "=r"(a) : "l"(p));
    return a;
}
#define CP_ASYNC16(d, s) \
    asm volatile("cp.async.cg.shared.global [%0], [%1], 16;" :: "r"(d), "l"(s))
#define CP_COMMIT() asm volatile("cp.async.commit_group;")
#define CP_WAIT0()  asm volatile("cp.async.wait_group 0;")
#define CP_WAIT1()  asm volatile("cp.async.wait_group 1;")

#define LDSM4(r, addr) \
    asm volatile("ldmatrix.sync.aligned.m8n8.x4.shared.b16 {%0,%1,%2,%3}, [%4];" \
        : "=r"((r)[0]), "=r"((r)[1]), "=r"((r)[2]), "=r"((r)[3]) : "r"(addr))

__device__ __forceinline__ void mma_f16(float* c, const uint32_t* a, uint32_t b0, uint32_t b1) {
    asm volatile(
        "mma.sync.aligned.m16n8k16.row.col.f32.f16.f16.f32 "
        "{%0,%1,%2,%3}, {%4,%5,%6,%7}, {%8,%9}, {%0,%1,%2,%3};"
        : "+f"(c[0]), "+f"(c[1]), "+f"(c[2]), "+f"(c[3])
        : "r"(a[0]), "r"(a[1]), "r"(a[2]), "r"(a[3]), "r"(b0), "r"(b1));
}

// ---------------- fused prepass: convert z, W1, W2 in ONE launch -------------
#define Z_ITEMS  ((size_t)BATCH * D_DIM / 8)          // 2097152
#define W1_ITEMS ((size_t)W_DIM * D_DIM / 8)          // 32768
#define W2_ITEMS ((size_t)D_DIM * W_DIM / 8)          // 32768
#define PREP_ITEMS (Z_ITEMS + W1_ITEMS + W2_ITEMS)    // 2162688 = 8448*256

union PackH8 { uint4 u; __half h[8]; };

__global__ void prep_kernel(const float* __restrict__ z,
                            const float* __restrict__ W1,
                            const float* __restrict__ W2) {
    size_t gid = (size_t)blockIdx.x * 256 + threadIdx.x;
    const float* src;
    __half* dst;
    float scale;
    size_t idx;
    if (gid < Z_ITEMS) {
        src = z;  dst = g_zh;  scale = 1.0f;  idx = gid;
    } else if (gid < Z_ITEMS + W1_ITEMS) {
        src = W1; dst = g_w1s; scale = WSCALE; idx = gid - Z_ITEMS;
    } else {
        src = W2; dst = g_w2s; scale = WSCALE; idx = gid - Z_ITEMS - W1_ITEMS;
    }
    const float4* s = reinterpret_cast<const float4*>(src);
    float4 a = s[idx * 2], b = s[idx * 2 + 1];
    float v[8] = {a.x, a.y, a.z, a.w, b.x, b.y, b.z, b.w};
    PackH8 o;
    #pragma unroll
    for (int i = 0; i < 8; i++) o.h[i] = __float2half_rn(v[i] * scale);
    reinterpret_cast<uint4*>(dst)[idx] = o.u;
}

__global__ void compute_M_kernel(const float* __restrict__ W1, const float* __restrict__ W2) {
    int j = blockIdx.x, i = threadIdx.x;
    float v = W1[j * D_DIM + i] * W2[(size_t)i * W_DIM + j];
    #pragma unroll
    for (int o = 16; o > 0; o >>= 1) v += __shfl_down_sync(0xffffffffu, v, o);
    __shared__ float red[8];
    if ((i & 31) == 0) red[i >> 5] = v;
    __syncthreads();
    if (i < 8) {
        float s = red[i];
        #pragma unroll
        for (int o = 4; o > 0; o >>= 1) s += __shfl_down_sync(0xffu, s, o);
        if (i == 0) g_M[j] = s;
    }
}

// ---------------- copy helpers (cp.async, 512 threads, swizzled dst) ---------
// nrows x 256 fp16 (512B rows)
__device__ __forceinline__ void cp_tile512(uint32_t sdst, const __half* g, int nrows) {
    const int total = nrows * 32;
    for (int i = threadIdx.x; i < total; i += NTHREADS) {
        int r = i >> 5, cu = i & 31;
        CP_ASYNC16(sdst + r * 512 + ((cu ^ (r & 7)) << 4), g + r * 256 + cu * 8);
    }
}
// 256 rows x 128 fp16 (256B rows), src rows stride W_DIM
__device__ __forceinline__ void cp_tileW2(uint32_t sdst, const __half* g) {
    for (int i = threadIdx.x; i < 4096; i += NTHREADS) {
        int r = i >> 4, cu = i & 15;
        CP_ASYNC16(sdst + r * 256 + ((cu ^ (r & 7)) << 4), g + (size_t)r * W_DIM + cu * 8);
    }
}

// ---------------- main fused kernel ----------------
__global__ void __launch_bounds__(NTHREADS, 1)
planar_mma_kernel(const float* __restrict__ b1,
                  float* __restrict__ dz_out,
                  float* __restrict__ dlog_out) {
    extern __shared__ char smem[];
    const uint32_t sb = smem_u32(smem);
    float* sTr = reinterpret_cast<float*>(smem + TR_OFF);

    const int tid  = threadIdx.x;
    const int wid  = tid >> 5;
    const int lane = tid & 31;
    const int mg   = wid >> 2;     // 0..3 : rows 32*mg .. +31
    const int ng   = wid & 3;      // GEMM1: 32 cols; GEMM2: 64 cols

    // tail-split tile mapping
    const int bid = blockIdx.x;
    int row0, ra;                  // tile row base, active rows
    if (bid < NFULL) { row0 = bid * MTILE;                       ra = MTILE; }
    else             { row0 = ROWS_FULL_TOTAL + (bid - NFULL) * 64; ra = 64; }
    const bool act = (mg * 32) < ra;   // warp-uniform

    if (tid < MTILE) sTr[tid] = 0.0f;

    // prologue: z (ra rows) + chunk-0 weights
    cp_tile512(sb + Z_S, g_zh + (size_t)row0 * D_DIM, ra);
    cp_tile512(sb + W1_S, g_w1s, 128);
    cp_tileW2(sb + W2_S, g_w2s);
    CP_COMMIT();
    CP_WAIT0();
    __syncthreads();

    // per-lane fragment addressing (XOR swizzle; swz == lane&7 for all reads)
    const int lr    = lane & 15;
    const int kodd  = lane >> 4;
    const int brow  = (lane & 7) + ((lane >> 4) << 3);
    const int koddb = (lane >> 3) & 1;
    const int swz   = lane & 7;

    const uint32_t zbase  = sb + Z_S  + (mg * 32 + lr) * 512;
    const uint32_t w1base = sb + W1_S + (ng * 32 + brow) * 512;
    const uint32_t hbase  = sb + H_S  + (mg * 32 + lr) * 256;
    const uint32_t w2base = sb + W2_S + (ng * 64 + brow) * 256;

    float dz[2][8][4];
    #pragma unroll
    for (int a = 0; a < 2; a++)
        #pragma unroll
        for (int b = 0; b < 8; b++)
            #pragma unroll
            for (int c = 0; c < 4; c++) dz[a][b][c] = 0.0f;
    float tr4[4] = {0.f, 0.f, 0.f, 0.f};

    for (int ch = 0; ch < NCHUNK; ch++) {
        const int jc = ch * CW;

        // ---------- GEMM1: pre = z @ (64*W1chunk)^T, warp m32n32 --------------
        float pre[2][4][4];
        if (act) {
            #pragma unroll
            for (int a = 0; a < 2; a++)
                #pragma unroll
                for (int b = 0; b < 4; b++)
                    #pragma unroll
                    for (int c = 0; c < 4; c++) pre[a][b][c] = 0.0f;

            #pragma unroll 8
            for (int ks = 0; ks < 16; ks++) {
                const uint32_t offA = (uint32_t)(((ks * 2 + kodd)  ^ swz) << 4);
                const uint32_t offB = (uint32_t)(((ks * 2 + koddb) ^ swz) << 4);
                uint32_t ah0[4], ah1[4], bh0[4], bh1[4];
                LDSM4(ah0, zbase + offA);
                LDSM4(ah1, zbase + 16 * 512 + offA);
                LDSM4(bh0, w1base + offB);
                LDSM4(bh1, w1base + 16 * 512 + offB);
                mma_f16(pre[0][0], ah0, bh0[0], bh0[1]);
                mma_f16(pre[0][1], ah0, bh0[2], bh0[3]);
                mma_f16(pre[0][2], ah0, bh1[0], bh1[1]);
                mma_f16(pre[0][3], ah0, bh1[2], bh1[3]);
                mma_f16(pre[1][0], ah1, bh0[0], bh0[1]);
                mma_f16(pre[1][1], ah1, bh0[2], bh0[3]);
                mma_f16(pre[1][2], ah1, bh1[0], bh1[1]);
                mma_f16(pre[1][3], ah1, bh1[2], bh1[3]);
            }

            // -------- epilogue: x = pre/64 + b1; softplus -> h; trace ---------
            #pragma unroll
            for (int mf = 0; mf < 2; mf++) {
                #pragma unroll
                for (int nf = 0; nf < 4; nf++) {
                    const int j0 = jc + ng * 32 + nf * 8 + 2 * (lane & 3);
                    const float b10 = __ldg(&b1[j0]),   b11 = __ldg(&b1[j0 + 1]);
                    const float M0  = g_M[j0],          M1  = g_M[j0 + 1];
                    const int clu = ng * 4 + nf;
                    #pragma unroll
                    for (int bq = 0; bq < 2; bq++) {
                        float x0 = fmaf(pre[mf][nf][2 * bq],     WINV, b10);
                        float x1 = fmaf(pre[mf][nf][2 * bq + 1], WINV, b11);
                        float e0 = __expf(-fabsf(x0)), e1 = __expf(-fabsf(x1));
                        float sp0 = fmaxf(x0, 0.0f) + __logf(1.0f + e0);
                        float sp1 = fmaxf(x1, 0.0f) + __logf(1.0f + e1);
                        float i0 = __fdividef(1.0f, 1.0f + e0);
                        float i1 = __fdividef(1.0f, 1.0f + e1);
                        float sg0 = (x0 >= 0.0f) ? i0 : e0 * i0;
                        float sg1 = (x1 >= 0.0f) ? i1 : e1 * i1;
                        tr4[mf * 2 + bq] = fmaf(sg0, M0, tr4[mf * 2 + bq]);
                        tr4[mf * 2 + bq] = fmaf(sg1, M1, tr4[mf * 2 + bq]);
                        __half h0 = __float2half_rn(sp0);
                        __half h1 = __float2half_rn(sp1);
                        uint32_t phi = ((uint32_t)__half_as_ushort(h1) << 16) |
                                       (uint32_t)__half_as_ushort(h0);
                        const int rl = mg * 32 + mf * 16 + (lane >> 2) + 8 * bq;
                        const uint32_t ha = sb + H_S + rl * 256 +
                                            (((uint32_t)(clu ^ (rl & 7))) << 4) +
                                            (lane & 3) * 4;
                        asm volatile("st.shared.b32 [%0], %1;" :: "r"(ha), "r"(phi) : "memory");
                    }
                }
            }
        }

        // wait for W2(ch) (issued at tail of ch-1; only group in flight)
        CP_WAIT0();
        __syncthreads();   // AB: past GEMM1 (W1 free), h written, W2(ch) visible

        // issue W1(ch+1): hidden under GEMM2(ch)
        if (ch + 1 < NCHUNK) {
            cp_tile512(sb + W1_S, g_w1s + (size_t)(jc + CW) * D_DIM, 128);
            CP_COMMIT();
        }

        // ---------- GEMM2: dz += h @ (64*W2chunk), warp m32n64, K=128 ---------
        if (act) {
            #pragma unroll
            for (int ks = 0; ks < 8; ks++) {
                const uint32_t offA = (uint32_t)(((ks * 2 + kodd)  ^ swz) << 4);
                const uint32_t offB = (uint32_t)(((ks * 2 + koddb) ^ swz) << 4);
                uint32_t ah0[4], ah1[4];
                LDSM4(ah0, hbase + offA);
                LDSM4(ah1, hbase + 16 * 256 + offA);
                #pragma unroll
                for (int t = 0; t < 4; t++) {
                    uint32_t bh[4];
                    LDSM4(bh, w2base + t * 16 * 256 + offB);
                    mma_f16(dz[0][2 * t],     ah0, bh[0], bh[1]);
                    mma_f16(dz[0][2 * t + 1], ah0, bh[2], bh[3]);
                    mma_f16(dz[1][2 * t],     ah1, bh[0], bh[1]);
                    mma_f16(dz[1][2 * t + 1], ah1, bh[2], bh[3]);
                }
            }
        }

        __syncthreads();   // C: all warps past GEMM2 -> W2 buffer free

        // issue W2(ch+1): in flight across chunk boundary; wait only W1(ch+1)
        if (ch + 1 < NCHUNK) {
            cp_tileW2(sb + W2_S, g_w2s + jc + CW);
            CP_COMMIT();
            CP_WAIT1();        // W1(ch+1) done; W2(ch+1) still in flight
            __syncthreads();   // D: W1(ch+1) visible
        }
    }

    // ---------------- writeout (undo weight scale) ----------------
    if (act) {
        #pragma unroll
        for (int mf = 0; mf < 2; mf++) {
            const int rl = mg * 32 + mf * 16 + (lane >> 2);
            #pragma unroll
            for (int nf = 0; nf < 8; nf++) {
                const int col = ng * 64 + nf * 8 + 2 * (lane & 3);
                float2 v0 = make_float2(dz[mf][nf][0] * WINV, dz[mf][nf][1] * WINV);
                float2 v1 = make_float2(dz[mf][nf][2] * WINV, dz[mf][nf][3] * WINV);
                *reinterpret_cast<float2*>(dz_out + (size_t)(row0 + rl) * D_DIM + col) = v0;
                *reinterpret_cast<float2*>(dz_out + (size_t)(row0 + rl + 8) * D_DIM + col) = v1;
            }
        }
        #pragma unroll
        for (int i = 0; i < 4; i++) {
            const int rl = mg * 32 + (i >> 1) * 16 + (lane >> 2) + 8 * (i & 1);
            atomicAdd(&sTr[rl], tr4[i]);
        }
    }
    __syncthreads();
    if (tid < ra) dlog_out[row0 + tid] = -sTr[tid];
}

// ---------------------------------------------------------------------------
extern "C" void kernel_launch(void* const* d_in, const int* in_sizes, int n_in,
                              void* d_out, int out_size) {
    const float* z  = (const float*)d_in[1];
    const float* W1 = (const float*)d_in[2];
    const float* b1 = (const float*)d_in[3];
    const float* W2 = (const float*)d_in[4];

    float* dz   = (float*)d_out;
    float* dlog = dz + (size_t)BATCH * D_DIM;

    prep_kernel<<<(int)(PREP_ITEMS / 256), 256>>>(z, W1, W2);
    compute_M_kernel<<<W_DIM, 256>>>(W1, W2);

    cudaFuncSetAttribute(planar_mma_kernel,
                         cudaFuncAttributeMaxDynamicSharedMemorySize, S_TOTAL);
    planar_mma_kernel<<<NGRID, NTHREADS, S_TOTAL>>>(b1, dz, dlog);
}

// round 12
// speedup vs baseline: 3.1653x; 1.0221x over previous
#include <cuda_runtime.h>
#include <cuda_fp16.h>
#include <stdint.h>
#include <math.h>

#define BATCH  65536
#define D_DIM  256
#define W_DIM  1024
#define MTILE  128
#define NTHREADS 512
#define CW     128
#define NCHUNK (W_DIM / CW)    // 8
#define WSCALE 64.0f
#define WINV   (1.0f / 64.0f)

// tail-split: 444 full tiles (128 rows) + 136 half tiles (64 rows)
#define NFULL  444
#define NHALF  136
#define NGRID  (NFULL + NHALF)          // 580
#define ROWS_FULL_TOTAL (NFULL * MTILE) // 56832

// device scratch: weights scaled fp16 (z is converted in-kernel now)
__device__ __align__(16) __half g_w1s[W_DIM * D_DIM];   // W1 * 64
__device__ __align__(16) __half g_w2s[D_DIM * W_DIM];   // W2 * 64
__device__ float g_M[W_DIM];

// ---------------- SMEM layout (bytes), XOR-swizzled, pad-free ----------------
#define Z_S    0
#define W1_S   65536
#define W2_S   131072
#define H_S    196608
#define TR_OFF 229376
#define S_TOTAL 229888

// ---------------- PTX helpers ----------------
__device__ __forceinline__ uint32_t smem_u32(const void* p) {
    uint32_t a;
    asm("{ .reg .u64 t; cvta.to.shared.u64 t, %1; cvt.u32.u64 %0, t; }" : "=r"(a) : "l"(p));
    return a;
}
#define CP_ASYNC16(d, s) \
    asm volatile("cp.async.cg.shared.global [%0], [%1], 16;" :: "r"(d), "l"(s))
#define CP_COMMIT() asm volatile("cp.async.commit_group;")
#define CP_WAIT0()  asm volatile("cp.async.wait_group 0;")
#define CP_WAIT1()  asm volatile("cp.async.wait_group 1;")

#define LDSM4(r, addr) \
    asm volatile("ldmatrix.sync.aligned.m8n8.x4.shared.b16 {%0,%1,%2,%3}, [%4];" \
        : "=r"((r)[0]), "=r"((r)[1]), "=r"((r)[2]), "=r"((r)[3]) : "r"(addr))

__device__ __forceinline__ void mma_f16(float* c, const uint32_t* a, uint32_t b0, uint32_t b1) {
    asm volatile(
        "mma.sync.aligned.m16n8k16.row.col.f32.f16.f16.f32 "
        "{%0,%1,%2,%3}, {%4,%5,%6,%7}, {%8,%9}, {%0,%1,%2,%3};"
        : "+f"(c[0]), "+f"(c[1]), "+f"(c[2]), "+f"(c[3])
        : "r"(a[0]), "r"(a[1]), "r"(a[2]), "r"(a[3]), "r"(b0), "r"(b1));
}

// ---------------- fused prepass: weights conv + M, ONE launch ----------------
// blocks [0,256): convert W1+W2 (65536 uint4 items, 256/block)
// blocks [256,1280): compute M[j], j = bid-256
#define WCONV_BLOCKS 256

union PackH8 { uint4 u; __half h[8]; };

__global__ void prep_kernel(const float* __restrict__ W1,
                            const float* __restrict__ W2) {
    if (blockIdx.x < WCONV_BLOCKS) {
        size_t gid = (size_t)blockIdx.x * 256 + threadIdx.x;   // 65536 items
        const float* src;
        __half* dst;
        size_t idx;
        if (gid < 32768) { src = W1; dst = g_w1s; idx = gid; }
        else             { src = W2; dst = g_w2s; idx = gid - 32768; }
        const float4* s = reinterpret_cast<const float4*>(src);
        float4 a = s[idx * 2], b = s[idx * 2 + 1];
        float v[8] = {a.x, a.y, a.z, a.w, b.x, b.y, b.z, b.w};
        PackH8 o;
        #pragma unroll
        for (int i = 0; i < 8; i++) o.h[i] = __float2half_rn(v[i] * WSCALE);
        reinterpret_cast<uint4*>(dst)[idx] = o.u;
    } else {
        int j = blockIdx.x - WCONV_BLOCKS, i = threadIdx.x;
        float v = W1[j * D_DIM + i] * W2[(size_t)i * W_DIM + j];
        #pragma unroll
        for (int o = 16; o > 0; o >>= 1) v += __shfl_down_sync(0xffffffffu, v, o);
        __shared__ float red[8];
        if ((i & 31) == 0) red[i >> 5] = v;
        __syncthreads();
        if (i < 8) {
            float s = red[i];
            #pragma unroll
            for (int o = 4; o > 0; o >>= 1) s += __shfl_down_sync(0xffu, s, o);
            if (i == 0) g_M[j] = s;
        }
    }
}

// ---------------- copy helpers (cp.async, 512 threads, swizzled dst) ---------
__device__ __forceinline__ void cp_tile512(uint32_t sdst, const __half* g, int nrows) {
    const int total = nrows * 32;
    for (int i = threadIdx.x; i < total; i += NTHREADS) {
        int r = i >> 5, cu = i & 31;
        CP_ASYNC16(sdst + r * 512 + ((cu ^ (r & 7)) << 4), g + r * 256 + cu * 8);
    }
}
__device__ __forceinline__ void cp_tileW2(uint32_t sdst, const __half* g) {
    for (int i = threadIdx.x; i < 4096; i += NTHREADS) {
        int r = i >> 4, cu = i & 15;
        CP_ASYNC16(sdst + r * 256 + ((cu ^ (r & 7)) << 4), g + (size_t)r * W_DIM + cu * 8);
    }
}

// ---------------- main fused kernel ----------------
__global__ void __launch_bounds__(NTHREADS, 1)
planar_mma_kernel(const float* __restrict__ z,
                  const float* __restrict__ b1,
                  float* __restrict__ dz_out,
                  float* __restrict__ dlog_out) {
    extern __shared__ char smem[];
    const uint32_t sb = smem_u32(smem);
    float* sTr = reinterpret_cast<float*>(smem + TR_OFF);

    const int tid  = threadIdx.x;
    const int wid  = tid >> 5;
    const int lane = tid & 31;
    const int mg   = wid >> 2;     // 0..3 : rows 32*mg .. +31
    const int ng   = wid & 3;      // GEMM1: 32 cols; GEMM2: 64 cols

    // tail-split tile mapping
    const int bid = blockIdx.x;
    int row0, ra;
    if (bid < NFULL) { row0 = bid * MTILE;                          ra = MTILE; }
    else             { row0 = ROWS_FULL_TOTAL + (bid - NFULL) * 64; ra = 64; }
    const bool act = (mg * 32) < ra;   // warp-uniform

    if (tid < MTILE) sTr[tid] = 0.0f;

    // prologue: weights via cp.async; z fp32 -> fp16 converted inline (overlaps)
    cp_tile512(sb + W1_S, g_w1s, 128);
    cp_tileW2(sb + W2_S, g_w2s);
    CP_COMMIT();
    {
        const float4* zg = reinterpret_cast<const float4*>(z + (size_t)row0 * D_DIM);
        const int total = ra * 32;
        for (int i = tid; i < total; i += NTHREADS) {
            int r = i >> 5, cu = i & 31;
            float4 a = zg[r * 64 + cu * 2];
            float4 b = zg[r * 64 + cu * 2 + 1];
            float v[8] = {a.x, a.y, a.z, a.w, b.x, b.y, b.z, b.w};
            PackH8 o;
            #pragma unroll
            for (int q = 0; q < 8; q++) o.h[q] = __float2half_rn(v[q]);
            const uint32_t da = sb + Z_S + r * 512 + ((cu ^ (r & 7)) << 4);
            asm volatile("st.shared.v4.b32 [%0], {%1,%2,%3,%4};"
                :: "r"(da), "r"(o.u.x), "r"(o.u.y), "r"(o.u.z), "r"(o.u.w) : "memory");
        }
    }
    CP_WAIT0();
    __syncthreads();

    // per-lane fragment addressing (XOR swizzle; swz == lane&7 for all reads)
    const int lr    = lane & 15;
    const int kodd  = lane >> 4;
    const int brow  = (lane & 7) + ((lane >> 4) << 3);
    const int koddb = (lane >> 3) & 1;
    const int swz   = lane & 7;

    const uint32_t zbase  = sb + Z_S  + (mg * 32 + lr) * 512;
    const uint32_t w1base = sb + W1_S + (ng * 32 + brow) * 512;
    const uint32_t hbase  = sb + H_S  + (mg * 32 + lr) * 256;
    const uint32_t w2base = sb + W2_S + (ng * 64 + brow) * 256;

    float dz[2][8][4];
    #pragma unroll
    for (int a = 0; a < 2; a++)
        #pragma unroll
        for (int b = 0; b < 8; b++)
            #pragma unroll
            for (int c = 0; c < 4; c++) dz[a][b][c] = 0.0f;
    float tr4[4] = {0.f, 0.f, 0.f, 0.f};

    for (int ch = 0; ch < NCHUNK; ch++) {
        const int jc = ch * CW;

        // ---------- GEMM1: pre = z @ (64*W1chunk)^T, warp m32n32 --------------
        float pre[2][4][4];
        if (act) {
            #pragma unroll
            for (int a = 0; a < 2; a++)
                #pragma unroll
                for (int b = 0; b < 4; b++)
                    #pragma unroll
                    for (int c = 0; c < 4; c++) pre[a][b][c] = 0.0f;

            #pragma unroll 8
            for (int ks = 0; ks < 16; ks++) {
                const uint32_t offA = (uint32_t)(((ks * 2 + kodd)  ^ swz) << 4);
                const uint32_t offB = (uint32_t)(((ks * 2 + koddb) ^ swz) << 4);
                uint32_t ah0[4], ah1[4], bh0[4], bh1[4];
                LDSM4(ah0, zbase + offA);
                LDSM4(ah1, zbase + 16 * 512 + offA);
                LDSM4(bh0, w1base + offB);
                LDSM4(bh1, w1base + 16 * 512 + offB);
                mma_f16(pre[0][0], ah0, bh0[0], bh0[1]);
                mma_f16(pre[0][1], ah0, bh0[2], bh0[3]);
                mma_f16(pre[0][2], ah0, bh1[0], bh1[1]);
                mma_f16(pre[0][3], ah0, bh1[2], bh1[3]);
                mma_f16(pre[1][0], ah1, bh0[0], bh0[1]);
                mma_f16(pre[1][1], ah1, bh0[2], bh0[3]);
                mma_f16(pre[1][2], ah1, bh1[0], bh1[1]);
                mma_f16(pre[1][3], ah1, bh1[2], bh1[3]);
            }

            // -------- epilogue: x = pre/64 + b1; softplus -> h; trace ---------
            #pragma unroll
            for (int mf = 0; mf < 2; mf++) {
                #pragma unroll
                for (int nf = 0; nf < 4; nf++) {
                    const int j0 = jc + ng * 32 + nf * 8 + 2 * (lane & 3);
                    const float b10 = __ldg(&b1[j0]),   b11 = __ldg(&b1[j0 + 1]);
                    const float M0  = g_M[j0],          M1  = g_M[j0 + 1];
                    const int clu = ng * 4 + nf;
                    #pragma unroll
                    for (int bq = 0; bq < 2; bq++) {
                        float x0 = fmaf(pre[mf][nf][2 * bq],     WINV, b10);
                        float x1 = fmaf(pre[mf][nf][2 * bq + 1], WINV, b11);
                        float e0 = __expf(-fabsf(x0)), e1 = __expf(-fabsf(x1));
                        float sp0 = fmaxf(x0, 0.0f) + __logf(1.0f + e0);
                        float sp1 = fmaxf(x1, 0.0f) + __logf(1.0f + e1);
                        float i0 = __fdividef(1.0f, 1.0f + e0);
                        float i1 = __fdividef(1.0f, 1.0f + e1);
                        float sg0 = (x0 >= 0.0f) ? i0 : e0 * i0;
                        float sg1 = (x1 >= 0.0f) ? i1 : e1 * i1;
                        tr4[mf * 2 + bq] = fmaf(sg0, M0, tr4[mf * 2 + bq]);
                        tr4[mf * 2 + bq] = fmaf(sg1, M1, tr4[mf * 2 + bq]);
                        __half h0 = __float2half_rn(sp0);
                        __half h1 = __float2half_rn(sp1);
                        uint32_t phi = ((uint32_t)__half_as_ushort(h1) << 16) |
                                       (uint32_t)__half_as_ushort(h0);
                        const int rl = mg * 32 + mf * 16 + (lane >> 2) + 8 * bq;
                        const uint32_t ha = sb + H_S + rl * 256 +
                                            (((uint32_t)(clu ^ (rl & 7))) << 4) +
                                            (lane & 3) * 4;
                        asm volatile("st.shared.b32 [%0], %1;" :: "r"(ha), "r"(phi) : "memory");
                    }
                }
            }
        }

        // wait for W2(ch) (issued at tail of ch-1; only group in flight)
        CP_WAIT0();
        __syncthreads();   // AB: past GEMM1 (W1 free), h written, W2(ch) visible

        // issue W1(ch+1): hidden under GEMM2(ch)
        if (ch + 1 < NCHUNK) {
            cp_tile512(sb + W1_S, g_w1s + (size_t)(jc + CW) * D_DIM, 128);
            CP_COMMIT();
        }

        // ---------- GEMM2: dz += h @ (64*W2chunk), warp m32n64, K=128 ---------
        if (act) {
            #pragma unroll
            for (int ks = 0; ks < 8; ks++) {
                const uint32_t offA = (uint32_t)(((ks * 2 + kodd)  ^ swz) << 4);
                const uint32_t offB = (uint32_t)(((ks * 2 + koddb) ^ swz) << 4);
                uint32_t ah0[4], ah1[4];
                LDSM4(ah0, hbase + offA);
                LDSM4(ah1, hbase + 16 * 256 + offA);
                #pragma unroll
                for (int t = 0; t < 4; t++) {
                    uint32_t bh[4];
                    LDSM4(bh, w2base + t * 16 * 256 + offB);
                    mma_f16(dz[0][2 * t],     ah0, bh[0], bh[1]);
                    mma_f16(dz[0][2 * t + 1], ah0, bh[2], bh[3]);
                    mma_f16(dz[1][2 * t],     ah1, bh[0], bh[1]);
                    mma_f16(dz[1][2 * t + 1], ah1, bh[2], bh[3]);
                }
            }
        }

        __syncthreads();   // C: all warps past GEMM2 -> W2 buffer free

        // issue W2(ch+1): in flight across chunk boundary; wait only W1(ch+1)
        if (ch + 1 < NCHUNK) {
            cp_tileW2(sb + W2_S, g_w2s + jc + CW);
            CP_COMMIT();
            CP_WAIT1();        // W1(ch+1) done; W2(ch+1) still in flight
            __syncthreads();   // D: W1(ch+1) visible
        }
    }

    // ---------------- writeout (undo weight scale) ----------------
    if (act) {
        #pragma unroll
        for (int mf = 0; mf < 2; mf++) {
            const int rl = mg * 32 + mf * 16 + (lane >> 2);
            #pragma unroll
            for (int nf = 0; nf < 8; nf++) {
                const int col = ng * 64 + nf * 8 + 2 * (lane & 3);
                float2 v0 = make_float2(dz[mf][nf][0] * WINV, dz[mf][nf][1] * WINV);
                float2 v1 = make_float2(dz[mf][nf][2] * WINV, dz[mf][nf][3] * WINV);
                *reinterpret_cast<float2*>(dz_out + (size_t)(row0 + rl) * D_DIM + col) = v0;
                *reinterpret_cast<float2*>(dz_out + (size_t)(row0 + rl + 8) * D_DIM + col) = v1;
            }
        }
        #pragma unroll
        for (int i = 0; i < 4; i++) {
            const int rl = mg * 32 + (i >> 1) * 16 + (lane >> 2) + 8 * (i & 1);
            atomicAdd(&sTr[rl], tr4[i]);
        }
    }
    __syncthreads();
    if (tid < ra) dlog_out[row0 + tid] = -sTr[tid];
}

// ---------------------------------------------------------------------------
extern "C" void kernel_launch(void* const* d_in, const int* in_sizes, int n_in,
                              void* d_out, int out_size) {
    const float* z  = (const float*)d_in[1];
    const float* W1 = (const float*)d_in[2];
    const float* b1 = (const float*)d_in[3];
    const float* W2 = (const float*)d_in[4];

    float* dz   = (float*)d_out;
    float* dlog = dz + (size_t)BATCH * D_DIM;

    prep_kernel<<<WCONV_BLOCKS + W_DIM, 256>>>(W1, W2);

    cudaFuncSetAttribute(planar_mma_kernel,
                         cudaFuncAttributeMaxDynamicSharedMemorySize, S_TOTAL);
    planar_mma_kernel<<<NGRID, NTHREADS, S_TOTAL>>>(z, b1, dz, dlog);
}